// round 5
// baseline (speedup 1.0000x reference)
#include <cuda_runtime.h>
#include <math.h>
#include <stdint.h>

#define QLEN 512
#define BATCH 4
#define DMODEL 1024
#define NLAYER 4
#define NHEAD 16
#define DHEAD 64
#define DINNER 4096
#define MLEN 512
#define KLEN 1024
#define BH (BATCH*NHEAD)

// ---------------- scratch ----------------
__device__ float g_cat[(size_t)KLEN*BATCH*DMODEL];
__device__ float g_heads[(size_t)KLEN*BATCH*3*DMODEL];
__device__ float g_r[(size_t)KLEN*DMODEL];
__device__ float g_rk[(size_t)KLEN*DMODEL];
__device__ float g_ac[(size_t)BH*QLEN*KLEN];
__device__ float g_bd[(size_t)BH*QLEN*KLEN];
__device__ float g_av[(size_t)QLEN*BATCH*DMODEL];
__device__ float g_tmp[(size_t)QLEN*BATCH*DMODEL];
__device__ float g_h[(size_t)QLEN*BATCH*DMODEL];
__device__ float g_ff[(size_t)QLEN*BATCH*DINNER];
__device__ float g_qu[(size_t)BH*QLEN*DHEAD];
__device__ float g_qv[(size_t)BH*QLEN*DHEAD];
__device__ float g_kc[(size_t)BH*KLEN*DHEAD];
__device__ float g_vc[(size_t)BH*KLEN*DHEAD];
__device__ float g_rkc[(size_t)NHEAD*KLEN*DHEAD];

__device__ __forceinline__ uint32_t f2tf32(float f) {
    uint32_t o;
    asm("cvt.rna.tf32.f32 %0, %1;" : "=r"(o) : "f"(f));
    return o;
}

#define MMA_TF32(d, a, b) \
    asm volatile("mma.sync.aligned.m16n8k8.row.col.f32.tf32.tf32.f32 " \
                 "{%0,%1,%2,%3}, {%4,%5,%6,%7}, {%8,%9}, {%0,%1,%2,%3};" \
                 : "+f"(d[0]), "+f"(d[1]), "+f"(d[2]), "+f"(d[3]) \
                 : "r"(a.x), "r"(a.y), "r"(a.z), "r"(a.w), "r"(b.x), "r"(b.y))

// A-side permuted STS: thread row ar (0..127), k base akb, element (c,e)
#define STS_A(Ap, c, e, val) do { \
    int k_ = akb + (c) * 4 + (e); \
    (Ap)[((a_wm * 4 + (k_ >> 3)) * 2 + a_mi) * 132 + \
         (a_lr * 4 + (k_ & 3)) * 4 + a_rh + 2 * ((k_ >> 2) & 1)] = f2tf32(val); \
} while (0)
// B-side permuted STS: thread k row bk, n base bn0, element (c,e)
#define STS_B(Bp, c, e, val) do { \
    int n_ = bn0 + (c) * 4 + (e); \
    (Bp)[(((n_ >> 5) * 4 + b_kk) * 4 + ((n_ >> 3) & 3)) * 66 + \
         ((n_ & 7) * 4 + b_lc) * 2 + b_kh] = f2tf32(val); \
} while (0)

#define SMEM_WORDS_PER_BUF 6336     // A 4224 + B 2112
#define GEMM2_SMEM (2 * SMEM_WORDS_PER_BUF * 4)

// ============ pipelined tf32 GEMM: C[.,N] = A[.,K] @ B[K,N], tile 128x64 ============
// 8 warps as 4(M)x2(N), warp tile 32x32. Double-buffered smem, register prefetch.
template<int RELU, int HASBIAS>
__global__ void __launch_bounds__(256, 2) gemm2(
    const float* __restrict__ A, const float* __restrict__ B,
    const float* __restrict__ bias, float* __restrict__ C,
    int K, int lda, int ldb, int ldc)
{
    extern __shared__ uint32_t dsm[];
    const int tid = threadIdx.x, lane = tid & 31, warp = tid >> 5;
    const int wm = warp >> 1, wn = warp & 1;
    const int bx = blockIdx.x, by = blockIdx.y;

    const int ar = tid >> 1, akb = (tid & 1) * 16;
    const int a_wm = ar >> 5, a_mi = (ar >> 4) & 1, a_lr = ar & 7, a_rh = (ar >> 3) & 1;
    const float* Ag = A + (size_t)(by * 128 + ar) * lda + akb;

    const int bk = tid & 31, bn0 = (tid >> 5) * 8;
    const int b_kk = bk >> 3, b_lc = bk & 3, b_kh = (bk >> 2) & 1;
    const float* Bg = B + (size_t)bk * ldb + bx * 64 + bn0;

    float acc[2][4][4];
#pragma unroll
    for (int mi = 0; mi < 2; mi++)
#pragma unroll
        for (int ni = 0; ni < 4; ni++)
#pragma unroll
            for (int r = 0; r < 4; r++) acc[mi][ni][r] = 0.f;

    const int lr = lane >> 2, lc = lane & 3;
    const int niter = K >> 5;

    float4 a_st[4]; float4 b_st[2];
#pragma unroll
    for (int c = 0; c < 4; c++) a_st[c] = *(const float4*)(Ag + c * 4);
#pragma unroll
    for (int c = 0; c < 2; c++) b_st[c] = *(const float4*)(Bg + c * 4);
    {
        uint32_t* Ap = dsm; uint32_t* Bp = dsm + 4224;
#pragma unroll
        for (int c = 0; c < 4; c++) {
            STS_A(Ap, c, 0, a_st[c].x); STS_A(Ap, c, 1, a_st[c].y);
            STS_A(Ap, c, 2, a_st[c].z); STS_A(Ap, c, 3, a_st[c].w);
        }
#pragma unroll
        for (int c = 0; c < 2; c++) {
            STS_B(Bp, c, 0, b_st[c].x); STS_B(Bp, c, 1, b_st[c].y);
            STS_B(Bp, c, 2, b_st[c].z); STS_B(Bp, c, 3, b_st[c].w);
        }
    }
    __syncthreads();

    for (int it = 0; it < niter; it++) {
        uint32_t* Ap = dsm + (it & 1) * SMEM_WORDS_PER_BUF;
        uint32_t* Bp = Ap + 4224;
        if (it + 1 < niter) {
            int k0 = (it + 1) * 32;
#pragma unroll
            for (int c = 0; c < 4; c++) a_st[c] = *(const float4*)(Ag + k0 + c * 4);
#pragma unroll
            for (int c = 0; c < 2; c++) b_st[c] = *(const float4*)(Bg + (size_t)k0 * ldb + c * 4);
        }
#pragma unroll
        for (int kk = 0; kk < 4; kk++) {
            uint4 af[2]; uint2 bf[4];
#pragma unroll
            for (int mi = 0; mi < 2; mi++)
                af[mi] = *(const uint4*)&Ap[((wm * 4 + kk) * 2 + mi) * 132 + lane * 4];
#pragma unroll
            for (int ni = 0; ni < 4; ni++)
                bf[ni] = *(const uint2*)&Bp[((wn * 4 + kk) * 4 + ni) * 66 + lane * 2];
#pragma unroll
            for (int mi = 0; mi < 2; mi++)
#pragma unroll
                for (int ni = 0; ni < 4; ni++) MMA_TF32(acc[mi][ni], af[mi], bf[ni]);
        }
        if (it + 1 < niter) {
            uint32_t* An = dsm + ((it + 1) & 1) * SMEM_WORDS_PER_BUF;
            uint32_t* Bn = An + 4224;
#pragma unroll
            for (int c = 0; c < 4; c++) {
                STS_A(An, c, 0, a_st[c].x); STS_A(An, c, 1, a_st[c].y);
                STS_A(An, c, 2, a_st[c].z); STS_A(An, c, 3, a_st[c].w);
            }
#pragma unroll
            for (int c = 0; c < 2; c++) {
                STS_B(Bn, c, 0, b_st[c].x); STS_B(Bn, c, 1, b_st[c].y);
                STS_B(Bn, c, 2, b_st[c].z); STS_B(Bn, c, 3, b_st[c].w);
            }
        }
        __syncthreads();
    }

#pragma unroll
    for (int mi = 0; mi < 2; mi++)
#pragma unroll
        for (int ni = 0; ni < 4; ni++) {
            int row0 = by * 128 + wm * 32 + mi * 16 + lr;
            int col  = bx * 64 + wn * 32 + ni * 8 + lc * 2;
            float b0 = 0.f, b1 = 0.f;
            if (HASBIAS) { b0 = bias[col]; b1 = bias[col + 1]; }
            float v0 = acc[mi][ni][0] + b0, v1 = acc[mi][ni][1] + b1;
            float v2 = acc[mi][ni][2] + b0, v3 = acc[mi][ni][3] + b1;
            if (RELU) {
                v0 = fmaxf(v0, 0.f); v1 = fmaxf(v1, 0.f);
                v2 = fmaxf(v2, 0.f); v3 = fmaxf(v3, 0.f);
            }
            *(float2*)(C + (size_t)row0 * ldc + col)       = make_float2(v0, v1);
            *(float2*)(C + (size_t)(row0 + 8) * ldc + col) = make_float2(v2, v3);
        }
}

// ---------------- small kernels ----------------
__global__ void posemb_kernel(float* __restrict__ r) {
    int idx = blockIdx.x * 256 + threadIdx.x;
    int k = idx >> 10, d = idx & 1023;
    float pos = (float)(KLEN - 1 - k);
    int j = (d < 512) ? d : d - 512;
    float inv = expf(-((float)(2 * j) / 1024.0f) * 9.210340371976184f);
    float ang = pos * inv;
    r[idx] = (d < 512) ? sinf(ang) : cosf(ang);
}

__global__ void copy4_kernel(float4* __restrict__ dst, const float4* __restrict__ src) {
    size_t i = (size_t)blockIdx.x * 256 + threadIdx.x;
    dst[i] = src[i];
}

__global__ void concat_kernel(float4* __restrict__ cat, const float4* __restrict__ mem,
                              const float4* __restrict__ h) {
    size_t i = (size_t)blockIdx.x * 256 + threadIdx.x;
    const size_t half = (size_t)MLEN * BATCH * DMODEL / 4;
    cat[i] = (i < half) ? mem[i] : h[i - half];
}

__global__ void repack_quqv(const float* __restrict__ heads, const float* __restrict__ u,
                            const float* __restrict__ v, float* __restrict__ qu,
                            float* __restrict__ qv) {
    int idx = blockIdx.x * 256 + threadIdx.x;
    int d4 = idx & 15, i = (idx >> 4) & 511, bh = idx >> 13;
    int b = bh >> 4, n = bh & 15;
    float4 q = *(const float4*)(heads + ((size_t)((512 + i) * 4 + b)) * 3072 + n * 64 + d4 * 4);
    float4 uu = *(const float4*)(u + n * 64 + d4 * 4);
    float4 vv = *(const float4*)(v + n * 64 + d4 * 4);
    size_t o = ((size_t)bh * 512 + i) * 64 + d4 * 4;
    *(float4*)(qu + o) = make_float4(q.x + uu.x, q.y + uu.y, q.z + uu.z, q.w + uu.w);
    *(float4*)(qv + o) = make_float4(q.x + vv.x, q.y + vv.y, q.z + vv.z, q.w + vv.w);
}

__global__ void repack_kv(const float* __restrict__ heads, float* __restrict__ kc,
                          float* __restrict__ vc) {
    int idx = blockIdx.x * 256 + threadIdx.x;
    int d4 = idx & 15, j = (idx >> 4) & 1023, bh = idx >> 14;
    int b = bh >> 4, n = bh & 15;
    const float* base = heads + ((size_t)(j * 4 + b)) * 3072 + n * 64 + d4 * 4;
    float4 kx = *(const float4*)(base + 1024);
    float4 vx = *(const float4*)(base + 2048);
    size_t o = ((size_t)bh * 1024 + j) * 64 + d4 * 4;
    *(float4*)(kc + o) = kx;
    *(float4*)(vc + o) = vx;
}

__global__ void repack_rk(const float* __restrict__ rk, float* __restrict__ rkc) {
    int idx = blockIdx.x * 256 + threadIdx.x;
    int d4 = idx & 15, j = (idx >> 4) & 1023, n = idx >> 14;
    *(float4*)(rkc + ((size_t)n * 1024 + j) * 64 + d4 * 4) =
        *(const float4*)(rk + (size_t)j * 1024 + n * 64 + d4 * 4);
}

// ---------------- score MMA (A @ B^T, K=64) ----------------
__global__ void __launch_bounds__(256, 2) score_mma(
    const float* __restrict__ Qb, const float* __restrict__ Kb,
    float* __restrict__ out, int mode)
{
    const int bx = blockIdx.x, by = blockIdx.y, bh = blockIdx.z;
    const int i0 = by * 128, j0 = bx * 128;
    if (mode == 0) { if (j0 >= i0 + 640) return; }
    else           { if (i0 + j0 < 257) return; }
    const float* A = Qb + (size_t)bh * QLEN * 64;
    const float* B = Kb + (size_t)(mode ? (bh & 15) : bh) * KLEN * 64;

    __shared__ uint32_t Ap[4224];
    __shared__ uint32_t Bp[4224];
    const int tid = threadIdx.x, lane = tid & 31;
    const int warp = tid >> 5, wm = warp >> 2, wn = warp & 3;

    const int ar = tid >> 1, akb = (tid & 1) * 16;
    const int a_wm = ar >> 6, a_mi = (ar >> 4) & 3, a_lr = ar & 7, a_rh = (ar >> 3) & 1;
    const float* Ag = A + (size_t)(i0 + ar) * 64 + akb;
    const float* Bg = B + (size_t)(j0 + ar) * 64 + akb;
    const int b_wn = ar >> 5, b_ni = (ar >> 3) & 3, b_lnr = ar & 7;

    float acc[4][4][4];
#pragma unroll
    for (int mi = 0; mi < 4; mi++)
#pragma unroll
        for (int ni = 0; ni < 4; ni++)
#pragma unroll
            for (int r = 0; r < 4; r++) acc[mi][ni][r] = 0.f;

    const int lr = lane >> 2, lc = lane & 3;

#pragma unroll
    for (int k0 = 0; k0 < 64; k0 += 32) {
#pragma unroll
        for (int c = 0; c < 4; c++) {
            float4 a4 = *(const float4*)(Ag + k0 + c * 4);
            float4 b4 = *(const float4*)(Bg + k0 + c * 4);
            float va[4] = {a4.x, a4.y, a4.z, a4.w};
            float vb[4] = {b4.x, b4.y, b4.z, b4.w};
#pragma unroll
            for (int e = 0; e < 4; e++) {
                int k = akb + c * 4 + e;
                int kk = k >> 3, klc = k & 3, kh = (k >> 2) & 1;
                Ap[((a_wm * 4 + kk) * 4 + a_mi) * 132 +
                   (a_lr * 4 + klc) * 4 + a_rh + 2 * kh] = f2tf32(va[e]);
                Bp[((b_wn * 4 + kk) * 4 + b_ni) * 66 +
                   (b_lnr * 4 + klc) * 2 + kh] = f2tf32(vb[e]);
            }
        }
        __syncthreads();
#pragma unroll
        for (int kk = 0; kk < 4; kk++) {
            uint4 af[4]; uint2 bf[4];
#pragma unroll
            for (int mi = 0; mi < 4; mi++)
                af[mi] = *(const uint4*)&Ap[((wm * 4 + kk) * 4 + mi) * 132 + lane * 4];
#pragma unroll
            for (int ni = 0; ni < 4; ni++)
                bf[ni] = *(const uint2*)&Bp[((wn * 4 + kk) * 4 + ni) * 66 + lane * 2];
#pragma unroll
            for (int mi = 0; mi < 4; mi++)
#pragma unroll
                for (int ni = 0; ni < 4; ni++) MMA_TF32(acc[mi][ni], af[mi], bf[ni]);
        }
        __syncthreads();
    }

    float* ob = out + (size_t)bh * QLEN * KLEN;
#pragma unroll
    for (int mi = 0; mi < 4; mi++)
#pragma unroll
        for (int ni = 0; ni < 4; ni++) {
            int row0 = i0 + wm * 64 + mi * 16 + lr;
            int col  = j0 + wn * 32 + ni * 8 + lc * 2;
            *(float2*)(ob + (size_t)row0 * KLEN + col) =
                make_float2(acc[mi][ni][0], acc[mi][ni][1]);
            *(float2*)(ob + (size_t)(row0 + 8) * KLEN + col) =
                make_float2(acc[mi][ni][2], acc[mi][ni][3]);
        }
}

// ---------------- softmax ----------------
__global__ void __launch_bounds__(256) softmax_kernel(float* ac, const float* __restrict__ bd) {
    int i = blockIdx.x;
    int bh = blockIdx.y;
    float* acrow = ac + ((size_t)bh * QLEN + i) * KLEN;
    const float* bdrow = bd + ((size_t)bh * QLEN + i) * KLEN;
    int tid = threadIdx.x;
    __shared__ float red[256];
    int jmax = i + MLEN;
    int shift = QLEN - 1 - i;
    float v[4];
    float m = -1e30f;
#pragma unroll
    for (int c = 0; c < 4; c++) {
        int j = c * 256 + tid;
        float s = (j <= jmax) ? 0.125f * (acrow[j] + bdrow[j + shift]) : -1e30f;
        v[c] = s;
        m = fmaxf(m, s);
    }
    red[tid] = m; __syncthreads();
    for (int o = 128; o > 0; o >>= 1) {
        if (tid < o) red[tid] = fmaxf(red[tid], red[tid + o]);
        __syncthreads();
    }
    m = red[0]; __syncthreads();
    float sum = 0.f;
#pragma unroll
    for (int c = 0; c < 4; c++) { v[c] = expf(v[c] - m); sum += v[c]; }
    red[tid] = sum; __syncthreads();
    for (int o = 128; o > 0; o >>= 1) {
        if (tid < o) red[tid] += red[tid + o];
        __syncthreads();
    }
    float inv = 1.0f / red[0];
#pragma unroll
    for (int c = 0; c < 4; c++) acrow[c * 256 + tid] = v[c] * inv;
}

// ---------------- AV MMA, pipelined (tile 128x64, warp 32x32) ----------------
__global__ void __launch_bounds__(256, 2) av_mma2(
    const float* __restrict__ P, const float* __restrict__ V, float* __restrict__ av)
{
    extern __shared__ uint32_t dsm[];
    const int by = blockIdx.x, bh = blockIdx.y;
    const int b = bh >> 4, n = bh & 15;
    const float* A = P + (size_t)bh * QLEN * KLEN + (size_t)by * 128 * KLEN;
    const float* Bv = V + (size_t)bh * KLEN * 64;
    const int kmax = min(KLEN, by * 128 + 640);

    const int tid = threadIdx.x, lane = tid & 31, warp = tid >> 5;
    const int wm = warp >> 1, wn = warp & 1;

    const int ar = tid >> 1, akb = (tid & 1) * 16;
    const int a_wm = ar >> 5, a_mi = (ar >> 4) & 1, a_lr = ar & 7, a_rh = (ar >> 3) & 1;
    const float* Ag = A + (size_t)ar * KLEN + akb;

    const int bk = tid & 31, bn0 = (tid >> 5) * 8;
    const int b_kk = bk >> 3, b_lc = bk & 3, b_kh = (bk >> 2) & 1;
    const float* Bg = Bv + (size_t)bk * 64 + bn0;

    float acc[2][4][4];
#pragma unroll
    for (int mi = 0; mi < 2; mi++)
#pragma unroll
        for (int ni = 0; ni < 4; ni++)
#pragma unroll
            for (int r = 0; r < 4; r++) acc[mi][ni][r] = 0.f;

    const int lr = lane >> 2, lc = lane & 3;
    const int niter = kmax >> 5;

    float4 a_st[4]; float4 b_st[2];
#pragma unroll
    for (int c = 0; c < 4; c++) a_st[c] = *(const float4*)(Ag + c * 4);
#pragma unroll
    for (int c = 0; c < 2; c++) b_st[c] = *(const float4*)(Bg + c * 4);
    {
        uint32_t* Ap = dsm; uint32_t* Bp = dsm + 4224;
#pragma unroll
        for (int c = 0; c < 4; c++) {
            STS_A(Ap, c, 0, a_st[c].x); STS_A(Ap, c, 1, a_st[c].y);
            STS_A(Ap, c, 2, a_st[c].z); STS_A(Ap, c, 3, a_st[c].w);
        }
#pragma unroll
        for (int c = 0; c < 2; c++) {
            STS_B(Bp, c, 0, b_st[c].x); STS_B(Bp, c, 1, b_st[c].y);
            STS_B(Bp, c, 2, b_st[c].z); STS_B(Bp, c, 3, b_st[c].w);
        }
    }
    __syncthreads();

    for (int it = 0; it < niter; it++) {
        uint32_t* Ap = dsm + (it & 1) * SMEM_WORDS_PER_BUF;
        uint32_t* Bp = Ap + 4224;
        if (it + 1 < niter) {
            int k0 = (it + 1) * 32;
#pragma unroll
            for (int c = 0; c < 4; c++) a_st[c] = *(const float4*)(Ag + k0 + c * 4);
#pragma unroll
            for (int c = 0; c < 2; c++) b_st[c] = *(const float4*)(Bg + (size_t)k0 * 64 + c * 4);
        }
#pragma unroll
        for (int kk = 0; kk < 4; kk++) {
            uint4 af[2]; uint2 bf[4];
#pragma unroll
            for (int mi = 0; mi < 2; mi++)
                af[mi] = *(const uint4*)&Ap[((wm * 4 + kk) * 2 + mi) * 132 + lane * 4];
#pragma unroll
            for (int ni = 0; ni < 4; ni++)
                bf[ni] = *(const uint2*)&Bp[((wn * 4 + kk) * 4 + ni) * 66 + lane * 2];
#pragma unroll
            for (int mi = 0; mi < 2; mi++)
#pragma unroll
                for (int ni = 0; ni < 4; ni++) MMA_TF32(acc[mi][ni], af[mi], bf[ni]);
        }
        if (it + 1 < niter) {
            uint32_t* An = dsm + ((it + 1) & 1) * SMEM_WORDS_PER_BUF;
            uint32_t* Bn = An + 4224;
#pragma unroll
            for (int c = 0; c < 4; c++) {
                STS_A(An, c, 0, a_st[c].x); STS_A(An, c, 1, a_st[c].y);
                STS_A(An, c, 2, a_st[c].z); STS_A(An, c, 3, a_st[c].w);
            }
#pragma unroll
            for (int c = 0; c < 2; c++) {
                STS_B(Bn, c, 0, b_st[c].x); STS_B(Bn, c, 1, b_st[c].y);
                STS_B(Bn, c, 2, b_st[c].z); STS_B(Bn, c, 3, b_st[c].w);
            }
        }
        __syncthreads();
    }

#pragma unroll
    for (int mi = 0; mi < 2; mi++)
#pragma unroll
        for (int ni = 0; ni < 4; ni++) {
            int row0 = by * 128 + wm * 32 + mi * 16 + lr;
            int col  = wn * 32 + ni * 8 + lc * 2;
            *(float2*)(av + ((size_t)row0 * 4 + b) * 1024 + n * 64 + col) =
                make_float2(acc[mi][ni][0], acc[mi][ni][1]);
            *(float2*)(av + ((size_t)(row0 + 8) * 4 + b) * 1024 + n * 64 + col) =
                make_float2(acc[mi][ni][2], acc[mi][ni][3]);
        }
}

// ---------------- residual add + LayerNorm ----------------
__global__ void __launch_bounds__(256) add_ln_kernel(
    float* __restrict__ h, const float* __restrict__ t,
    const float* __restrict__ g, const float* __restrict__ b)
{
    int row = blockIdx.x;
    int tid = threadIdx.x;
    __shared__ float rs[256], rs2[256];
    float x[4];
    float s = 0.f, ss = 0.f;
#pragma unroll
    for (int c = 0; c < 4; c++) {
        int d = c * 256 + tid;
        float v = h[(size_t)row * 1024 + d] + t[(size_t)row * 1024 + d];
        x[c] = v; s += v; ss += v * v;
    }
    rs[tid] = s; rs2[tid] = ss; __syncthreads();
    for (int o = 128; o > 0; o >>= 1) {
        if (tid < o) { rs[tid] += rs[tid + o]; rs2[tid] += rs2[tid + o]; }
        __syncthreads();
    }
    float mu = rs[0] * (1.0f / 1024.0f);
    float var = rs2[0] * (1.0f / 1024.0f) - mu * mu;
    float inv = rsqrtf(var + 1e-5f);
#pragma unroll
    for (int c = 0; c < 4; c++) {
        int d = c * 256 + tid;
        h[(size_t)row * 1024 + d] = (x[c] - mu) * inv * g[d] + b[d];
    }
}

// ---------------- launch ----------------
extern "C" void kernel_launch(void* const* d_in, const int* in_sizes, int n_in,
                              void* d_out, int out_size) {
    (void)in_sizes; (void)n_in; (void)out_size;
    const float* x     = (const float*)d_in[0];
    const float* mems  = (const float*)d_in[1];
    const float* u     = (const float*)d_in[2];
    const float* v     = (const float*)d_in[3];
    const float* W_qkv = (const float*)d_in[4];
    const float* W_o   = (const float*)d_in[5];
    const float* W_r   = (const float*)d_in[6];
    const float* ln1_g = (const float*)d_in[7];
    const float* ln1_b = (const float*)d_in[8];
    const float* W1    = (const float*)d_in[9];
    const float* b1    = (const float*)d_in[10];
    const float* W2    = (const float*)d_in[11];
    const float* b2    = (const float*)d_in[12];
    const float* ln2_g = (const float*)d_in[13];
    const float* ln2_b = (const float*)d_in[14];

    float *cat, *heads, *r, *rk, *ac, *bd, *av, *tmp, *h, *ff, *qu, *qv, *kc, *vc, *rkc;
    cudaGetSymbolAddress((void**)&cat,   g_cat);
    cudaGetSymbolAddress((void**)&heads, g_heads);
    cudaGetSymbolAddress((void**)&r,     g_r);
    cudaGetSymbolAddress((void**)&rk,    g_rk);
    cudaGetSymbolAddress((void**)&ac,    g_ac);
    cudaGetSymbolAddress((void**)&bd,    g_bd);
    cudaGetSymbolAddress((void**)&av,    g_av);
    cudaGetSymbolAddress((void**)&tmp,   g_tmp);
    cudaGetSymbolAddress((void**)&h,     g_h);
    cudaGetSymbolAddress((void**)&ff,    g_ff);
    cudaGetSymbolAddress((void**)&qu,    g_qu);
    cudaGetSymbolAddress((void**)&qv,    g_qv);
    cudaGetSymbolAddress((void**)&kc,    g_kc);
    cudaGetSymbolAddress((void**)&vc,    g_vc);
    cudaGetSymbolAddress((void**)&rkc,   g_rkc);

    cudaFuncSetAttribute(gemm2<0,0>, cudaFuncAttributeMaxDynamicSharedMemorySize, GEMM2_SMEM);
    cudaFuncSetAttribute(gemm2<1,1>, cudaFuncAttributeMaxDynamicSharedMemorySize, GEMM2_SMEM);
    cudaFuncSetAttribute(gemm2<0,1>, cudaFuncAttributeMaxDynamicSharedMemorySize, GEMM2_SMEM);
    cudaFuncSetAttribute(av_mma2,    cudaFuncAttributeMaxDynamicSharedMemorySize, GEMM2_SMEM);

    posemb_kernel<<<4096, 256>>>(r);
    copy4_kernel<<<2048, 256>>>((float4*)h, (const float4*)x);

    for (int l = 0; l < NLAYER; l++) {
        const float* Wq = W_qkv + (size_t)l * DMODEL * 3072;
        concat_kernel<<<4096, 256>>>((float4*)cat,
                                     (const float4*)(mems + (size_t)l * MLEN * BATCH * DMODEL),
                                     (const float4*)h);
        // K,V: all 4096 rows, cols 1024..3071 of W_qkv
        gemm2<0,0><<<dim3(32, 32), 256, GEMM2_SMEM>>>(
            cat, Wq + 1024, nullptr, heads + 1024, 1024, 1024, 3072, 3072);
        // Q: last 2048 rows, cols 0..1023
        gemm2<0,0><<<dim3(16, 16), 256, GEMM2_SMEM>>>(
            cat + (size_t)2048 * 1024, Wq, nullptr, heads + (size_t)2048 * 3072,
            1024, 1024, 3072, 3072);
        // rk
        gemm2<0,0><<<dim3(16, 8), 256, GEMM2_SMEM>>>(
            r, W_r + (size_t)l * DMODEL * DMODEL, nullptr, rk, 1024, 1024, 1024, 1024);
        // repacks
        repack_quqv<<<2048, 256>>>(heads, u, v, qu, qv);
        repack_kv<<<4096, 256>>>(heads, kc, vc);
        repack_rk<<<1024, 256>>>(rk, rkc);
        // scores
        score_mma<<<dim3(8, 4, BH), 256>>>(qu, kc, ac, 0);
        score_mma<<<dim3(8, 4, BH), 256>>>(qv, rkc, bd, 1);
        softmax_kernel<<<dim3(QLEN, BH), 256>>>(ac, bd);
        av_mma2<<<dim3(4, BH), 256, GEMM2_SMEM>>>(ac, vc, av);
        // O projection
        gemm2<0,0><<<dim3(16, 16), 256, GEMM2_SMEM>>>(
            av, W_o + (size_t)l * DMODEL * DMODEL, nullptr, tmp, 1024, 1024, 1024, 1024);
        add_ln_kernel<<<2048, 256>>>(h, tmp, ln1_g + (size_t)l * DMODEL, ln1_b + (size_t)l * DMODEL);
        // FFN
        gemm2<1,1><<<dim3(64, 16), 256, GEMM2_SMEM>>>(
            h, W1 + (size_t)l * DMODEL * DINNER, b1 + (size_t)l * DINNER, ff,
            1024, 1024, 4096, 4096);
        gemm2<0,1><<<dim3(16, 16), 256, GEMM2_SMEM>>>(
            ff, W2 + (size_t)l * DINNER * DMODEL, b2 + (size_t)l * DMODEL, tmp,
            4096, 4096, 1024, 1024);
        add_ln_kernel<<<2048, 256>>>(h, tmp, ln2_g + (size_t)l * DMODEL, ln2_b + (size_t)l * DMODEL);
    }

    cudaMemcpyAsync(d_out, h, (size_t)QLEN * BATCH * DMODEL * sizeof(float),
                    cudaMemcpyDeviceToDevice);
}

// round 6
// speedup vs baseline: 1.2984x; 1.2984x over previous
#include <cuda_runtime.h>
#include <math.h>
#include <stdint.h>

#define QLEN 512
#define BATCH 4
#define DMODEL 1024
#define NLAYER 4
#define NHEAD 16
#define DHEAD 64
#define DINNER 4096
#define MLEN 512
#define KLEN 1024
#define BH (BATCH*NHEAD)

// ---------------- scratch ----------------
__device__ float g_cat[(size_t)KLEN*BATCH*DMODEL];
__device__ float g_heads[(size_t)KLEN*BATCH*3*DMODEL];
__device__ float g_r[(size_t)KLEN*DMODEL];
__device__ float g_rk[(size_t)KLEN*DMODEL];
__device__ float g_ac[(size_t)BH*QLEN*KLEN];
__device__ float g_bd[(size_t)BH*QLEN*KLEN];
__device__ float g_av[(size_t)QLEN*BATCH*DMODEL];
__device__ float g_tmp[(size_t)QLEN*BATCH*DMODEL];
__device__ float g_h[(size_t)QLEN*BATCH*DMODEL];
__device__ float g_ff[(size_t)QLEN*BATCH*DINNER];
__device__ float g_qu[(size_t)BH*QLEN*DHEAD];
__device__ float g_qv[(size_t)BH*QLEN*DHEAD];
__device__ float g_kc[(size_t)BH*KLEN*DHEAD];
__device__ float g_vc[(size_t)BH*KLEN*DHEAD];
__device__ float g_rkc[(size_t)NHEAD*KLEN*DHEAD];

__device__ __forceinline__ uint32_t f2tf32(float f) {
    uint32_t o;
    asm("cvt.rna.tf32.f32 %0, %1;" : "=r"(o) : "f"(f));
    return o;
}

#define MMA_TF32(d, a, b) \
    asm volatile("mma.sync.aligned.m16n8k8.row.col.f32.tf32.tf32.f32 " \
                 "{%0,%1,%2,%3}, {%4,%5,%6,%7}, {%8,%9}, {%0,%1,%2,%3};" \
                 : "+f"(d[0]), "+f"(d[1]), "+f"(d[2]), "+f"(d[3]) \
                 : "r"(a.x), "r"(a.y), "r"(a.z), "r"(a.w), "r"(b.x), "r"(b.y))

#define GEMM_BUF 8448           // A 4224 + B 4224 words per stage
#define GEMM_SMEM (2 * GEMM_BUF * 4)
#define AV_BUF 6336             // A 4224 + B 2112
#define AV_SMEM (2 * AV_BUF * 4)

// ============ pipelined NT GEMM: C = A[M,K] @ B[K,N], tile 128x128 ============
// 8 warps 2(M)x4(N), warp tile 64x32. Double-buffered smem, 1 sync/iter,
// LDG issued 2 iterations ahead of its STS.
template<int RELU, int HASBIAS>
__global__ void __launch_bounds__(256) gemm_nt(
    const float* __restrict__ A, const float* __restrict__ B,
    const float* __restrict__ bias, float* __restrict__ C,
    int K, int lda, int ldb, int ldc)
{
    extern __shared__ uint32_t dsm[];
    const int tid = threadIdx.x, lane = tid & 31;
    const int warp = tid >> 5, wm = warp >> 2, wn = warp & 3;
    const int bx = blockIdx.x, by = blockIdx.y;

    const int ar = tid >> 1, akb = (tid & 1) * 16;
    const int a_wm = ar >> 6, a_mi = (ar >> 4) & 3, a_lr = ar & 7, a_rh = (ar >> 3) & 1;
    const float* Ag = A + (size_t)(by * 128 + ar) * lda + akb;

    const int bk = tid & 31, bn0 = (tid >> 5) * 16;
    const int b_kk = bk >> 3, b_lc = bk & 3, b_kh = (bk >> 2) & 1;
    const float* Bg = B + (size_t)bk * ldb + bx * 128 + bn0;

    float acc[4][4][4];
#pragma unroll
    for (int mi = 0; mi < 4; mi++)
#pragma unroll
        for (int ni = 0; ni < 4; ni++)
#pragma unroll
            for (int r = 0; r < 4; r++) acc[mi][ni][r] = 0.f;

    const int lr = lane >> 2, lc = lane & 3;
    const int niter = K >> 5;

    float4 a_st[4], b_st[4];
#define G_LOAD(k0) do { \
    _Pragma("unroll") for (int c = 0; c < 4; c++) a_st[c] = *(const float4*)(Ag + (k0) + c * 4); \
    _Pragma("unroll") for (int c = 0; c < 4; c++) b_st[c] = *(const float4*)(Bg + (size_t)(k0) * ldb + c * 4); \
} while (0)
#define G_STS(buf) do { \
    uint32_t* Ap_ = (buf); uint32_t* Bp_ = (buf) + 4224; \
    _Pragma("unroll") for (int c = 0; c < 4; c++) { \
        float va[4] = {a_st[c].x, a_st[c].y, a_st[c].z, a_st[c].w}; \
        float vb[4] = {b_st[c].x, b_st[c].y, b_st[c].z, b_st[c].w}; \
        _Pragma("unroll") for (int e = 0; e < 4; e++) { \
            int k_ = akb + c * 4 + e; \
            Ap_[((a_wm * 4 + (k_ >> 3)) * 4 + a_mi) * 132 + \
                (a_lr * 4 + (k_ & 3)) * 4 + a_rh + 2 * ((k_ >> 2) & 1)] = f2tf32(va[e]); \
            int n_ = bn0 + c * 4 + e; \
            Bp_[(((n_ >> 5) * 4 + b_kk) * 4 + ((n_ >> 3) & 3)) * 66 + \
                ((n_ & 7) * 4 + b_lc) * 2 + b_kh] = f2tf32(vb[e]); \
        } \
    } \
} while (0)

    // prologue: tile0 -> buf0; tile1 LDG in flight
    G_LOAD(0);
    G_STS(dsm);
    if (niter > 1) G_LOAD(32);
    __syncthreads();

    for (int it = 0; it < niter; it++) {
        uint32_t* cur = dsm + (it & 1) * GEMM_BUF;
        if (it + 1 < niter) {
            uint32_t* nxt = dsm + ((it + 1) & 1) * GEMM_BUF;
            G_STS(nxt);
        }
        if (it + 2 < niter) G_LOAD((it + 2) * 32);
        uint32_t* Bpc = cur + 4224;
#pragma unroll
        for (int kk = 0; kk < 4; kk++) {
            uint4 af[4]; uint2 bf[4];
#pragma unroll
            for (int mi = 0; mi < 4; mi++)
                af[mi] = *(const uint4*)&cur[((wm * 4 + kk) * 4 + mi) * 132 + lane * 4];
#pragma unroll
            for (int ni = 0; ni < 4; ni++)
                bf[ni] = *(const uint2*)&Bpc[((wn * 4 + kk) * 4 + ni) * 66 + lane * 2];
#pragma unroll
            for (int mi = 0; mi < 4; mi++)
#pragma unroll
                for (int ni = 0; ni < 4; ni++) MMA_TF32(acc[mi][ni], af[mi], bf[ni]);
        }
        __syncthreads();
    }
#undef G_LOAD
#undef G_STS

#pragma unroll
    for (int mi = 0; mi < 4; mi++) {
#pragma unroll
        for (int ni = 0; ni < 4; ni++) {
            int row0 = by * 128 + wm * 64 + mi * 16 + lr;
            int col  = bx * 128 + wn * 32 + ni * 8 + lc * 2;
            float b0 = 0.f, b1 = 0.f;
            if (HASBIAS) { b0 = bias[col]; b1 = bias[col + 1]; }
            float v0 = acc[mi][ni][0] + b0, v1 = acc[mi][ni][1] + b1;
            float v2 = acc[mi][ni][2] + b0, v3 = acc[mi][ni][3] + b1;
            if (RELU) {
                v0 = fmaxf(v0, 0.f); v1 = fmaxf(v1, 0.f);
                v2 = fmaxf(v2, 0.f); v3 = fmaxf(v3, 0.f);
            }
            *(float2*)(C + (size_t)row0 * ldc + col)       = make_float2(v0, v1);
            *(float2*)(C + (size_t)(row0 + 8) * ldc + col) = make_float2(v2, v3);
        }
    }
}

// ---------------- small kernels ----------------
__global__ void posemb_kernel(float* __restrict__ r) {
    int idx = blockIdx.x * 256 + threadIdx.x;
    int k = idx >> 10, d = idx & 1023;
    float pos = (float)(KLEN - 1 - k);
    int j = (d < 512) ? d : d - 512;
    float inv = expf(-((float)(2 * j) / 1024.0f) * 9.210340371976184f);
    float ang = pos * inv;
    r[idx] = (d < 512) ? sinf(ang) : cosf(ang);
}

__global__ void copy4_kernel(float4* __restrict__ dst, const float4* __restrict__ src) {
    size_t i = (size_t)blockIdx.x * 256 + threadIdx.x;
    dst[i] = src[i];
}

__global__ void concat_kernel(float4* __restrict__ cat, const float4* __restrict__ mem,
                              const float4* __restrict__ h) {
    size_t i = (size_t)blockIdx.x * 256 + threadIdx.x;
    const size_t half = (size_t)MLEN * BATCH * DMODEL / 4;
    cat[i] = (i < half) ? mem[i] : h[i - half];
}

__global__ void repack_quqv(const float* __restrict__ heads, const float* __restrict__ u,
                            const float* __restrict__ v, float* __restrict__ qu,
                            float* __restrict__ qv) {
    int idx = blockIdx.x * 256 + threadIdx.x;
    int d4 = idx & 15, i = (idx >> 4) & 511, bh = idx >> 13;
    int b = bh >> 4, n = bh & 15;
    float4 q = *(const float4*)(heads + ((size_t)((512 + i) * 4 + b)) * 3072 + n * 64 + d4 * 4);
    float4 uu = *(const float4*)(u + n * 64 + d4 * 4);
    float4 vv = *(const float4*)(v + n * 64 + d4 * 4);
    size_t o = ((size_t)bh * 512 + i) * 64 + d4 * 4;
    *(float4*)(qu + o) = make_float4(q.x + uu.x, q.y + uu.y, q.z + uu.z, q.w + uu.w);
    *(float4*)(qv + o) = make_float4(q.x + vv.x, q.y + vv.y, q.z + vv.z, q.w + vv.w);
}

__global__ void repack_kv(const float* __restrict__ heads, float* __restrict__ kc,
                          float* __restrict__ vc) {
    int idx = blockIdx.x * 256 + threadIdx.x;
    int d4 = idx & 15, j = (idx >> 4) & 1023, bh = idx >> 14;
    int b = bh >> 4, n = bh & 15;
    const float* base = heads + ((size_t)(j * 4 + b)) * 3072 + n * 64 + d4 * 4;
    float4 kx = *(const float4*)(base + 1024);
    float4 vx = *(const float4*)(base + 2048);
    size_t o = ((size_t)bh * 1024 + j) * 64 + d4 * 4;
    *(float4*)(kc + o) = kx;
    *(float4*)(vc + o) = vx;
}

__global__ void repack_rk(const float* __restrict__ rk, float* __restrict__ rkc) {
    int idx = blockIdx.x * 256 + threadIdx.x;
    int d4 = idx & 15, j = (idx >> 4) & 1023, n = idx >> 14;
    *(float4*)(rkc + ((size_t)n * 1024 + j) * 64 + d4 * 4) =
        *(const float4*)(rk + (size_t)j * 1024 + n * 64 + d4 * 4);
}

// ---------------- score MMA (A @ B^T, K=64) — R3 version ----------------
__global__ void __launch_bounds__(256, 2) score_mma(
    const float* __restrict__ Qb, const float* __restrict__ Kb,
    float* __restrict__ out, int mode)
{
    const int bx = blockIdx.x, by = blockIdx.y, bh = blockIdx.z;
    const int i0 = by * 128, j0 = bx * 128;
    if (mode == 0) { if (j0 >= i0 + 640) return; }
    else           { if (i0 + j0 < 257) return; }
    const float* A = Qb + (size_t)bh * QLEN * 64;
    const float* B = Kb + (size_t)(mode ? (bh & 15) : bh) * KLEN * 64;

    __shared__ uint32_t Ap[4224];
    __shared__ uint32_t Bp[4224];
    const int tid = threadIdx.x, lane = tid & 31;
    const int warp = tid >> 5, wm = warp >> 2, wn = warp & 3;

    const int ar = tid >> 1, akb = (tid & 1) * 16;
    const int a_wm = ar >> 6, a_mi = (ar >> 4) & 3, a_lr = ar & 7, a_rh = (ar >> 3) & 1;
    const float* Ag = A + (size_t)(i0 + ar) * 64 + akb;
    const float* Bg = B + (size_t)(j0 + ar) * 64 + akb;
    const int b_wn = ar >> 5, b_ni = (ar >> 3) & 3, b_lnr = ar & 7;

    float acc[4][4][4];
#pragma unroll
    for (int mi = 0; mi < 4; mi++)
#pragma unroll
        for (int ni = 0; ni < 4; ni++)
#pragma unroll
            for (int r = 0; r < 4; r++) acc[mi][ni][r] = 0.f;

    const int lr = lane >> 2, lc = lane & 3;

#pragma unroll
    for (int k0 = 0; k0 < 64; k0 += 32) {
#pragma unroll
        for (int c = 0; c < 4; c++) {
            float4 a4 = *(const float4*)(Ag + k0 + c * 4);
            float4 b4 = *(const float4*)(Bg + k0 + c * 4);
            float va[4] = {a4.x, a4.y, a4.z, a4.w};
            float vb[4] = {b4.x, b4.y, b4.z, b4.w};
#pragma unroll
            for (int e = 0; e < 4; e++) {
                int k = akb + c * 4 + e;
                int kk = k >> 3, klc = k & 3, kh = (k >> 2) & 1;
                Ap[((a_wm * 4 + kk) * 4 + a_mi) * 132 +
                   (a_lr * 4 + klc) * 4 + a_rh + 2 * kh] = f2tf32(va[e]);
                Bp[((b_wn * 4 + kk) * 4 + b_ni) * 66 +
                   (b_lnr * 4 + klc) * 2 + kh] = f2tf32(vb[e]);
            }
        }
        __syncthreads();
#pragma unroll
        for (int kk = 0; kk < 4; kk++) {
            uint4 af[4]; uint2 bf[4];
#pragma unroll
            for (int mi = 0; mi < 4; mi++)
                af[mi] = *(const uint4*)&Ap[((wm * 4 + kk) * 4 + mi) * 132 + lane * 4];
#pragma unroll
            for (int ni = 0; ni < 4; ni++)
                bf[ni] = *(const uint2*)&Bp[((wn * 4 + kk) * 4 + ni) * 66 + lane * 2];
#pragma unroll
            for (int mi = 0; mi < 4; mi++)
#pragma unroll
                for (int ni = 0; ni < 4; ni++) MMA_TF32(acc[mi][ni], af[mi], bf[ni]);
        }
        __syncthreads();
    }

    float* ob = out + (size_t)bh * QLEN * KLEN;
#pragma unroll
    for (int mi = 0; mi < 4; mi++)
#pragma unroll
        for (int ni = 0; ni < 4; ni++) {
            int row0 = i0 + wm * 64 + mi * 16 + lr;
            int col  = j0 + wn * 32 + ni * 8 + lc * 2;
            *(float2*)(ob + (size_t)row0 * KLEN + col) =
                make_float2(acc[mi][ni][0], acc[mi][ni][1]);
            *(float2*)(ob + (size_t)(row0 + 8) * KLEN + col) =
                make_float2(acc[mi][ni][2], acc[mi][ni][3]);
        }
}

// ---------------- softmax ----------------
__global__ void __launch_bounds__(256) softmax_kernel(float* ac, const float* __restrict__ bd) {
    int i = blockIdx.x;
    int bh = blockIdx.y;
    float* acrow = ac + ((size_t)bh * QLEN + i) * KLEN;
    const float* bdrow = bd + ((size_t)bh * QLEN + i) * KLEN;
    int tid = threadIdx.x;
    __shared__ float red[256];
    int jmax = i + MLEN;
    int shift = QLEN - 1 - i;
    float v[4];
    float m = -1e30f;
#pragma unroll
    for (int c = 0; c < 4; c++) {
        int j = c * 256 + tid;
        float s = (j <= jmax) ? 0.125f * (acrow[j] + bdrow[j + shift]) : -1e30f;
        v[c] = s;
        m = fmaxf(m, s);
    }
    red[tid] = m; __syncthreads();
    for (int o = 128; o > 0; o >>= 1) {
        if (tid < o) red[tid] = fmaxf(red[tid], red[tid + o]);
        __syncthreads();
    }
    m = red[0]; __syncthreads();
    float sum = 0.f;
#pragma unroll
    for (int c = 0; c < 4; c++) { v[c] = expf(v[c] - m); sum += v[c]; }
    red[tid] = sum; __syncthreads();
    for (int o = 128; o > 0; o >>= 1) {
        if (tid < o) red[tid] += red[tid + o];
        __syncthreads();
    }
    float inv = 1.0f / red[0];
#pragma unroll
    for (int c = 0; c < 4; c++) acrow[c * 256 + tid] = v[c] * inv;
}

// ---------------- AV MMA, pipelined double-buffer (tile 128x64, warp 32x32) -------
__global__ void __launch_bounds__(256) av_mma(
    const float* __restrict__ P, const float* __restrict__ V, float* __restrict__ av)
{
    extern __shared__ uint32_t dsm[];
    const int by = blockIdx.x, bh = blockIdx.y;
    const int b = bh >> 4, n = bh & 15;
    const float* A = P + (size_t)bh * QLEN * KLEN + (size_t)by * 128 * KLEN;
    const float* Bv = V + (size_t)bh * KLEN * 64;
    const int kmax = min(KLEN, by * 128 + 640);

    const int tid = threadIdx.x, lane = tid & 31, warp = tid >> 5;
    const int wm = warp >> 1, wn = warp & 1;

    const int ar = tid >> 1, akb = (tid & 1) * 16;
    const int a_wm = ar >> 5, a_mi = (ar >> 4) & 1, a_lr = ar & 7, a_rh = (ar >> 3) & 1;
    const float* Ag = A + (size_t)ar * KLEN + akb;

    const int bk = tid & 31, bn0 = (tid >> 5) * 8;
    const int b_kk = bk >> 3, b_lc = bk & 3, b_kh = (bk >> 2) & 1;
    const float* Bg = Bv + (size_t)bk * 64 + bn0;

    float acc[2][4][4];
#pragma unroll
    for (int mi = 0; mi < 2; mi++)
#pragma unroll
        for (int ni = 0; ni < 4; ni++)
#pragma unroll
            for (int r = 0; r < 4; r++) acc[mi][ni][r] = 0.f;

    const int lr = lane >> 2, lc = lane & 3;
    const int niter = kmax >> 5;

    float4 a_st[4], b_st[2];
#define AV_LOAD(k0) do { \
    _Pragma("unroll") for (int c = 0; c < 4; c++) a_st[c] = *(const float4*)(Ag + (k0) + c * 4); \
    _Pragma("unroll") for (int c = 0; c < 2; c++) b_st[c] = *(const float4*)(Bg + (size_t)(k0) * 64 + c * 4); \
} while (0)
#define AV_STS(buf) do { \
    uint32_t* Ap_ = (buf); uint32_t* Bp_ = (buf) + 4224; \
    _Pragma("unroll") for (int c = 0; c < 4; c++) { \
        float va[4] = {a_st[c].x, a_st[c].y, a_st[c].z, a_st[c].w}; \
        _Pragma("unroll") for (int e = 0; e < 4; e++) { \
            int k_ = akb + c * 4 + e; \
            Ap_[((a_wm * 4 + (k_ >> 3)) * 2 + a_mi) * 132 + \
                (a_lr * 4 + (k_ & 3)) * 4 + a_rh + 2 * ((k_ >> 2) & 1)] = f2tf32(va[e]); \
        } \
    } \
    _Pragma("unroll") for (int c = 0; c < 2; c++) { \
        float vb[4] = {b_st[c].x, b_st[c].y, b_st[c].z, b_st[c].w}; \
        _Pragma("unroll") for (int e = 0; e < 4; e++) { \
            int n_ = bn0 + c * 4 + e; \
            Bp_[(((n_ >> 5) * 4 + b_kk) * 4 + ((n_ >> 3) & 3)) * 66 + \
                ((n_ & 7) * 4 + b_lc) * 2 + b_kh] = f2tf32(vb[e]); \
        } \
    } \
} while (0)

    AV_LOAD(0);
    AV_STS(dsm);
    if (niter > 1) AV_LOAD(32);
    __syncthreads();

    for (int it = 0; it < niter; it++) {
        uint32_t* cur = dsm + (it & 1) * AV_BUF;
        if (it + 1 < niter) {
            uint32_t* nxt = dsm + ((it + 1) & 1) * AV_BUF;
            AV_STS(nxt);
        }
        if (it + 2 < niter) AV_LOAD((it + 2) * 32);
        uint32_t* Bpc = cur + 4224;
#pragma unroll
        for (int kk = 0; kk < 4; kk++) {
            uint4 af[2]; uint2 bf[4];
#pragma unroll
            for (int mi = 0; mi < 2; mi++)
                af[mi] = *(const uint4*)&cur[((wm * 4 + kk) * 2 + mi) * 132 + lane * 4];
#pragma unroll
            for (int ni = 0; ni < 4; ni++)
                bf[ni] = *(const uint2*)&Bpc[((wn * 4 + kk) * 4 + ni) * 66 + lane * 2];
#pragma unroll
            for (int mi = 0; mi < 2; mi++)
#pragma unroll
                for (int ni = 0; ni < 4; ni++) MMA_TF32(acc[mi][ni], af[mi], bf[ni]);
        }
        __syncthreads();
    }
#undef AV_LOAD
#undef AV_STS

#pragma unroll
    for (int mi = 0; mi < 2; mi++)
#pragma unroll
        for (int ni = 0; ni < 4; ni++) {
            int row0 = by * 128 + wm * 32 + mi * 16 + lr;
            int col  = wn * 32 + ni * 8 + lc * 2;
            *(float2*)(av + ((size_t)row0 * 4 + b) * 1024 + n * 64 + col) =
                make_float2(acc[mi][ni][0], acc[mi][ni][1]);
            *(float2*)(av + ((size_t)(row0 + 8) * 4 + b) * 1024 + n * 64 + col) =
                make_float2(acc[mi][ni][2], acc[mi][ni][3]);
        }
}

// ---------------- residual add + LayerNorm ----------------
__global__ void __launch_bounds__(256) add_ln_kernel(
    float* __restrict__ h, const float* __restrict__ t,
    const float* __restrict__ g, const float* __restrict__ b)
{
    int row = blockIdx.x;
    int tid = threadIdx.x;
    __shared__ float rs[256], rs2[256];
    float x[4];
    float s = 0.f, ss = 0.f;
#pragma unroll
    for (int c = 0; c < 4; c++) {
        int d = c * 256 + tid;
        float v = h[(size_t)row * 1024 + d] + t[(size_t)row * 1024 + d];
        x[c] = v; s += v; ss += v * v;
    }
    rs[tid] = s; rs2[tid] = ss; __syncthreads();
    for (int o = 128; o > 0; o >>= 1) {
        if (tid < o) { rs[tid] += rs[tid + o]; rs2[tid] += rs2[tid + o]; }
        __syncthreads();
    }
    float mu = rs[0] * (1.0f / 1024.0f);
    float var = rs2[0] * (1.0f / 1024.0f) - mu * mu;
    float inv = rsqrtf(var + 1e-5f);
#pragma unroll
    for (int c = 0; c < 4; c++) {
        int d = c * 256 + tid;
        h[(size_t)row * 1024 + d] = (x[c] - mu) * inv * g[d] + b[d];
    }
}

// ---------------- launch ----------------
extern "C" void kernel_launch(void* const* d_in, const int* in_sizes, int n_in,
                              void* d_out, int out_size) {
    (void)in_sizes; (void)n_in; (void)out_size;
    const float* x     = (const float*)d_in[0];
    const float* mems  = (const float*)d_in[1];
    const float* u     = (const float*)d_in[2];
    const float* v     = (const float*)d_in[3];
    const float* W_qkv = (const float*)d_in[4];
    const float* W_o   = (const float*)d_in[5];
    const float* W_r   = (const float*)d_in[6];
    const float* ln1_g = (const float*)d_in[7];
    const float* ln1_b = (const float*)d_in[8];
    const float* W1    = (const float*)d_in[9];
    const float* b1    = (const float*)d_in[10];
    const float* W2    = (const float*)d_in[11];
    const float* b2    = (const float*)d_in[12];
    const float* ln2_g = (const float*)d_in[13];
    const float* ln2_b = (const float*)d_in[14];

    float *cat, *heads, *r, *rk, *ac, *bd, *av, *tmp, *h, *ff, *qu, *qv, *kc, *vc, *rkc;
    cudaGetSymbolAddress((void**)&cat,   g_cat);
    cudaGetSymbolAddress((void**)&heads, g_heads);
    cudaGetSymbolAddress((void**)&r,     g_r);
    cudaGetSymbolAddress((void**)&rk,    g_rk);
    cudaGetSymbolAddress((void**)&ac,    g_ac);
    cudaGetSymbolAddress((void**)&bd,    g_bd);
    cudaGetSymbolAddress((void**)&av,    g_av);
    cudaGetSymbolAddress((void**)&tmp,   g_tmp);
    cudaGetSymbolAddress((void**)&h,     g_h);
    cudaGetSymbolAddress((void**)&ff,    g_ff);
    cudaGetSymbolAddress((void**)&qu,    g_qu);
    cudaGetSymbolAddress((void**)&qv,    g_qv);
    cudaGetSymbolAddress((void**)&kc,    g_kc);
    cudaGetSymbolAddress((void**)&vc,    g_vc);
    cudaGetSymbolAddress((void**)&rkc,   g_rkc);

    cudaFuncSetAttribute(gemm_nt<0,0>, cudaFuncAttributeMaxDynamicSharedMemorySize, GEMM_SMEM);
    cudaFuncSetAttribute(gemm_nt<1,1>, cudaFuncAttributeMaxDynamicSharedMemorySize, GEMM_SMEM);
    cudaFuncSetAttribute(gemm_nt<0,1>, cudaFuncAttributeMaxDynamicSharedMemorySize, GEMM_SMEM);
    cudaFuncSetAttribute(av_mma,       cudaFuncAttributeMaxDynamicSharedMemorySize, AV_SMEM);

    posemb_kernel<<<4096, 256>>>(r);
    copy4_kernel<<<2048, 256>>>((float4*)h, (const float4*)x);

    for (int l = 0; l < NLAYER; l++) {
        const float* Wq = W_qkv + (size_t)l * DMODEL * 3072;
        concat_kernel<<<4096, 256>>>((float4*)cat,
                                     (const float4*)(mems + (size_t)l * MLEN * BATCH * DMODEL),
                                     (const float4*)h);
        // K,V: all 4096 rows, cols 1024..3071
        gemm_nt<0,0><<<dim3(16, 32), 256, GEMM_SMEM>>>(
            cat, Wq + 1024, nullptr, heads + 1024, 1024, 1024, 3072, 3072);
        // Q: last 2048 rows, cols 0..1023
        gemm_nt<0,0><<<dim3(8, 16), 256, GEMM_SMEM>>>(
            cat + (size_t)2048 * 1024, Wq, nullptr, heads + (size_t)2048 * 3072,
            1024, 1024, 3072, 3072);
        // rk
        gemm_nt<0,0><<<dim3(8, 8), 256, GEMM_SMEM>>>(
            r, W_r + (size_t)l * DMODEL * DMODEL, nullptr, rk, 1024, 1024, 1024, 1024);
        // repacks
        repack_quqv<<<2048, 256>>>(heads, u, v, qu, qv);
        repack_kv<<<4096, 256>>>(heads, kc, vc);
        repack_rk<<<1024, 256>>>(rk, rkc);
        // scores
        score_mma<<<dim3(8, 4, BH), 256>>>(qu, kc, ac, 0);
        score_mma<<<dim3(8, 4, BH), 256>>>(qv, rkc, bd, 1);
        softmax_kernel<<<dim3(QLEN, BH), 256>>>(ac, bd);
        av_mma<<<dim3(4, BH), 256, AV_SMEM>>>(ac, vc, av);
        // O projection
        gemm_nt<0,0><<<dim3(8, 16), 256, GEMM_SMEM>>>(
            av, W_o + (size_t)l * DMODEL * DMODEL, nullptr, tmp, 1024, 1024, 1024, 1024);
        add_ln_kernel<<<2048, 256>>>(h, tmp, ln1_g + (size_t)l * DMODEL, ln1_b + (size_t)l * DMODEL);
        // FFN
        gemm_nt<1,1><<<dim3(32, 16), 256, GEMM_SMEM>>>(
            h, W1 + (size_t)l * DMODEL * DINNER, b1 + (size_t)l * DINNER, ff,
            1024, 1024, 4096, 4096);
        gemm_nt<0,1><<<dim3(8, 16), 256, GEMM_SMEM>>>(
            ff, W2 + (size_t)l * DINNER * DMODEL, b2 + (size_t)l * DMODEL, tmp,
            4096, 4096, 1024, 1024);
        add_ln_kernel<<<2048, 256>>>(h, tmp, ln2_g + (size_t)l * DMODEL, ln2_b + (size_t)l * DMODEL);
    }

    cudaMemcpyAsync(d_out, h, (size_t)QLEN * BATCH * DMODEL * sizeof(float),
                    cudaMemcpyDeviceToDevice);
}

// round 7
// speedup vs baseline: 1.3911x; 1.0714x over previous
#include <cuda_runtime.h>
#include <math.h>
#include <stdint.h>

#define QLEN 512
#define BATCH 4
#define DMODEL 1024
#define NLAYER 4
#define NHEAD 16
#define DHEAD 64
#define DINNER 4096
#define MLEN 512
#define KLEN 1024
#define BH (BATCH*NHEAD)

// ---------------- scratch ----------------
__device__ float g_cat[(size_t)KLEN*BATCH*DMODEL];
__device__ float g_heads[(size_t)KLEN*BATCH*3*DMODEL];
__device__ float g_r[(size_t)KLEN*DMODEL];
__device__ float g_rk[(size_t)KLEN*DMODEL];
__device__ float g_ac[(size_t)BH*QLEN*KLEN];
__device__ float g_bd[(size_t)BH*QLEN*KLEN];
__device__ float g_av[(size_t)QLEN*BATCH*DMODEL];
__device__ float g_tmp[(size_t)QLEN*BATCH*DMODEL];
__device__ float g_h[(size_t)QLEN*BATCH*DMODEL];
__device__ float g_ff[(size_t)QLEN*BATCH*DINNER];
__device__ float g_qu[(size_t)BH*QLEN*DHEAD];
__device__ float g_qv[(size_t)BH*QLEN*DHEAD];
__device__ float g_kc[(size_t)BH*KLEN*DHEAD];
__device__ float g_vc[(size_t)BH*KLEN*DHEAD];
__device__ float g_rkc[(size_t)NHEAD*KLEN*DHEAD];

__device__ __forceinline__ uint32_t f2tf32(float f) {
    uint32_t o;
    asm("cvt.rna.tf32.f32 %0, %1;" : "=r"(o) : "f"(f));
    return o;
}
__device__ __forceinline__ float f2tf32f(float f) {
    uint32_t o = f2tf32(f);
    return __uint_as_float(o);
}

#define MMA_TF32(d, a, b) \
    asm volatile("mma.sync.aligned.m16n8k8.row.col.f32.tf32.tf32.f32 " \
                 "{%0,%1,%2,%3}, {%4,%5,%6,%7}, {%8,%9}, {%0,%1,%2,%3};" \
                 : "+f"(d[0]), "+f"(d[1]), "+f"(d[2]), "+f"(d[3]) \
                 : "r"(a.x), "r"(a.y), "r"(a.z), "r"(a.w), "r"(b.x), "r"(b.y))

__device__ __forceinline__ void cpasync16(uint32_t dst, const void* src) {
    asm volatile("cp.async.cg.shared.global [%0], [%1], 16;" :: "r"(dst), "l"(src));
}
#define CP_COMMIT() asm volatile("cp.async.commit_group;" ::: "memory")
#define CP_WAIT2()  asm volatile("cp.async.wait_group 2;" ::: "memory")
__device__ __forceinline__ uint32_t smem_u32(const void* p) {
    uint32_t a;
    asm("{ .reg .u64 t; cvta.to.shared.u64 t, %1; cvt.u32.u64 %0, t; }" : "=r"(a) : "l"(p));
    return a;
}
#define SW128B(o) ((o) ^ (((o) >> 3) & 0x70))

// gemm3 smem: A 4 stages x 8192 words (256rows x 128B swizzled), B 2 stages x 4224
#define A_STAGE_W 8192
#define B_STAGE_W 4224
#define B_BASE_W  (4 * A_STAGE_W)
#define GEMM3_SMEM ((4 * A_STAGE_W + 2 * B_STAGE_W) * 4)

// ======== gemm3: C[M,N]=A[M,K]@B[K,N]. CTA tile 256x128, warp 64x64, cp.async A ========
// A must be pre-rounded to tf32 values. B converted on STS.
template<int RELU, int HASBIAS, int CVT>
__global__ void __launch_bounds__(256) gemm3(
    const float* __restrict__ A, const float* __restrict__ B,
    const float* __restrict__ bias, float* __restrict__ C,
    int K, int lda, int ldb, int ldc)
{
    extern __shared__ uint32_t dsm[];
    const uint32_t sbase = smem_u32(dsm);
    const int tid = threadIdx.x, lane = tid & 31;
    const int warp = tid >> 5, wm = warp >> 1, wn = warp & 1;
    const int bx = blockIdx.x, by = blockIdx.y;

    // A cp.async mapping: 8 passes; pass i: row = (tid>>3) + 32*i, chunk = tid&7
    const int a_row0 = tid >> 3, a_ch = tid & 7;
    const float* Ag = A + (size_t)(by * 256 + a_row0) * lda + a_ch * 4;

    // B: LDG + permuted STS (with cvt)
    const int bk = tid & 31, bn0 = (tid >> 5) * 16;
    const int b_kk = bk >> 3, b_lc = bk & 3, b_kh = (bk >> 2) & 1;
    const float* Bg = B + (size_t)bk * ldb + bx * 128 + bn0;

    float acc[4][8][4];
#pragma unroll
    for (int mi = 0; mi < 4; mi++)
#pragma unroll
        for (int ni = 0; ni < 8; ni++)
#pragma unroll
            for (int r = 0; r < 4; r++) acc[mi][ni][r] = 0.f;

    const int lr = lane >> 2, lc = lane & 3;
    const int niter = K >> 5;

    float4 b_st[4];
#define B_LDG(k0) do { \
    _Pragma("unroll") for (int c = 0; c < 4; c++) \
        b_st[c] = *(const float4*)(Bg + (size_t)(k0) * ldb + c * 4); \
} while (0)
#define B_STS(stg) do { \
    uint32_t* Bp_ = dsm + B_BASE_W + (stg) * B_STAGE_W; \
    _Pragma("unroll") for (int c = 0; c < 4; c++) { \
        float vb[4] = {b_st[c].x, b_st[c].y, b_st[c].z, b_st[c].w}; \
        _Pragma("unroll") for (int e = 0; e < 4; e++) { \
            int n_ = bn0 + c * 4 + e; \
            Bp_[(((n_ >> 5) * 4 + b_kk) * 4 + ((n_ >> 3) & 3)) * 66 + \
                ((n_ & 7) * 4 + b_lc) * 2 + b_kh] = f2tf32(vb[e]); \
        } \
    } \
} while (0)
#define A_CPA(stg, k0) do { \
    uint32_t ab_ = sbase + (stg) * A_STAGE_W * 4; \
    _Pragma("unroll") for (int i = 0; i < 8; i++) { \
        uint32_t so_ = SW128B((uint32_t)((a_row0 + 32 * i) * 128 + a_ch * 16)); \
        cpasync16(ab_ + so_, Ag + (size_t)(32 * i) * lda + (k0)); \
    } \
    CP_COMMIT(); \
} while (0)

    // prologue
    B_LDG(0);
    A_CPA(0, 0);
    if (niter > 1) A_CPA(1, 32);
    if (niter > 2) A_CPA(2, 64);
    B_STS(0);
    if (niter > 1) B_LDG(32);
    CP_WAIT2();          // A stage 0 ready
    __syncthreads();

    for (int it = 0; it < niter; it++) {
        if (it + 1 < niter) B_STS((it + 1) & 1);
        if (it + 2 < niter) B_LDG((it + 2) * 32);
        if (it + 3 < niter) A_CPA((it + 3) & 3, (it + 3) * 32);

        const uint32_t* Abuf = dsm + (it & 3) * A_STAGE_W;
        const uint32_t* Bbuf = dsm + B_BASE_W + (it & 1) * B_STAGE_W;
#pragma unroll
        for (int kk = 0; kk < 4; kk++) {
            uint4 af[4]; uint2 bf[8];
#pragma unroll
            for (int mi = 0; mi < 4; mi++) {
                int row = wm * 64 + mi * 16 + lr;
                int k = kk * 8 + lc;
                uint32_t o00 = SW128B((uint32_t)(row * 128 + k * 4)) >> 2;
                uint32_t o10 = SW128B((uint32_t)((row + 8) * 128 + k * 4)) >> 2;
                uint32_t o01 = SW128B((uint32_t)(row * 128 + (k + 4) * 4)) >> 2;
                uint32_t o11 = SW128B((uint32_t)((row + 8) * 128 + (k + 4) * 4)) >> 2;
                af[mi].x = Abuf[o00];
                af[mi].y = Abuf[o10];
                af[mi].z = Abuf[o01];
                af[mi].w = Abuf[o11];
            }
#pragma unroll
            for (int ni = 0; ni < 8; ni++)
                bf[ni] = *(const uint2*)&Bbuf[(((wn * 2 + (ni >> 2)) * 4 + kk) * 4 + (ni & 3)) * 66 + lane * 2];
#pragma unroll
            for (int mi = 0; mi < 4; mi++)
#pragma unroll
                for (int ni = 0; ni < 8; ni++) MMA_TF32(acc[mi][ni], af[mi], bf[ni]);
        }
        CP_WAIT2();
        __syncthreads();
    }
#undef B_LDG
#undef B_STS
#undef A_CPA

#pragma unroll
    for (int mi = 0; mi < 4; mi++) {
#pragma unroll
        for (int ni = 0; ni < 8; ni++) {
            int row0 = by * 256 + wm * 64 + mi * 16 + lr;
            int col  = bx * 128 + wn * 64 + ni * 8 + lc * 2;
            float b0 = 0.f, b1 = 0.f;
            if (HASBIAS) { b0 = bias[col]; b1 = bias[col + 1]; }
            float v0 = acc[mi][ni][0] + b0, v1 = acc[mi][ni][1] + b1;
            float v2 = acc[mi][ni][2] + b0, v3 = acc[mi][ni][3] + b1;
            if (RELU) {
                v0 = fmaxf(v0, 0.f); v1 = fmaxf(v1, 0.f);
                v2 = fmaxf(v2, 0.f); v3 = fmaxf(v3, 0.f);
            }
            if (CVT) {
                v0 = f2tf32f(v0); v1 = f2tf32f(v1);
                v2 = f2tf32f(v2); v3 = f2tf32f(v3);
            }
            *(float2*)(C + (size_t)row0 * ldc + col)       = make_float2(v0, v1);
            *(float2*)(C + (size_t)(row0 + 8) * ldc + col) = make_float2(v2, v3);
        }
    }
}

// ---------------- small kernels ----------------
__global__ void posemb_kernel(float* __restrict__ r) {
    int idx = blockIdx.x * 256 + threadIdx.x;
    int k = idx >> 10, d = idx & 1023;
    float pos = (float)(KLEN - 1 - k);
    int j = (d < 512) ? d : d - 512;
    float inv = expf(-((float)(2 * j) / 1024.0f) * 9.210340371976184f);
    float ang = pos * inv;
    r[idx] = f2tf32f((d < 512) ? sinf(ang) : cosf(ang));
}

__global__ void copy4_kernel(float4* __restrict__ dst, const float4* __restrict__ src) {
    size_t i = (size_t)blockIdx.x * 256 + threadIdx.x;
    dst[i] = src[i];
}

// concat rounds to tf32 (cat is a gemm A operand)
__global__ void concat_kernel(float4* __restrict__ cat, const float4* __restrict__ mem,
                              const float4* __restrict__ h) {
    size_t i = (size_t)blockIdx.x * 256 + threadIdx.x;
    const size_t half = (size_t)MLEN * BATCH * DMODEL / 4;
    float4 v = (i < half) ? mem[i] : h[i - half];
    cat[i] = make_float4(f2tf32f(v.x), f2tf32f(v.y), f2tf32f(v.z), f2tf32f(v.w));
}

__global__ void repack_quqv(const float* __restrict__ heads, const float* __restrict__ u,
                            const float* __restrict__ v, float* __restrict__ qu,
                            float* __restrict__ qv) {
    int idx = blockIdx.x * 256 + threadIdx.x;
    int d4 = idx & 15, i = (idx >> 4) & 511, bh = idx >> 13;
    int b = bh >> 4, n = bh & 15;
    float4 q = *(const float4*)(heads + ((size_t)((512 + i) * 4 + b)) * 3072 + n * 64 + d4 * 4);
    float4 uu = *(const float4*)(u + n * 64 + d4 * 4);
    float4 vv = *(const float4*)(v + n * 64 + d4 * 4);
    size_t o = ((size_t)bh * 512 + i) * 64 + d4 * 4;
    *(float4*)(qu + o) = make_float4(q.x + uu.x, q.y + uu.y, q.z + uu.z, q.w + uu.w);
    *(float4*)(qv + o) = make_float4(q.x + vv.x, q.y + vv.y, q.z + vv.z, q.w + vv.w);
}

__global__ void repack_kv(const float* __restrict__ heads, float* __restrict__ kc,
                          float* __restrict__ vc) {
    int idx = blockIdx.x * 256 + threadIdx.x;
    int d4 = idx & 15, j = (idx >> 4) & 1023, bh = idx >> 14;
    int b = bh >> 4, n = bh & 15;
    const float* base = heads + ((size_t)(j * 4 + b)) * 3072 + n * 64 + d4 * 4;
    float4 kx = *(const float4*)(base + 1024);
    float4 vx = *(const float4*)(base + 2048);
    size_t o = ((size_t)bh * 1024 + j) * 64 + d4 * 4;
    *(float4*)(kc + o) = kx;
    *(float4*)(vc + o) = vx;
}

__global__ void repack_rk(const float* __restrict__ rk, float* __restrict__ rkc) {
    int idx = blockIdx.x * 256 + threadIdx.x;
    int d4 = idx & 15, j = (idx >> 4) & 1023, n = idx >> 14;
    *(float4*)(rkc + ((size_t)n * 1024 + j) * 64 + d4 * 4) =
        *(const float4*)(rk + (size_t)j * 1024 + n * 64 + d4 * 4);
}

// ---------------- score MMA (A @ B^T, K=64) ----------------
__global__ void __launch_bounds__(256, 2) score_mma(
    const float* __restrict__ Qb, const float* __restrict__ Kb,
    float* __restrict__ out, int mode)
{
    const int bx = blockIdx.x, by = blockIdx.y, bh = blockIdx.z;
    const int i0 = by * 128, j0 = bx * 128;
    if (mode == 0) { if (j0 >= i0 + 640) return; }
    else           { if (i0 + j0 < 257) return; }
    const float* A = Qb + (size_t)bh * QLEN * 64;
    const float* B = Kb + (size_t)(mode ? (bh & 15) : bh) * KLEN * 64;

    __shared__ uint32_t Ap[4224];
    __shared__ uint32_t Bp[4224];
    const int tid = threadIdx.x, lane = tid & 31;
    const int warp = tid >> 5, wm = warp >> 2, wn = warp & 3;

    const int ar = tid >> 1, akb = (tid & 1) * 16;
    const int a_wm = ar >> 6, a_mi = (ar >> 4) & 3, a_lr = ar & 7, a_rh = (ar >> 3) & 1;
    const float* Ag = A + (size_t)(i0 + ar) * 64 + akb;
    const float* Bg = B + (size_t)(j0 + ar) * 64 + akb;
    const int b_wn = ar >> 5, b_ni = (ar >> 3) & 3, b_lnr = ar & 7;

    float acc[4][4][4];
#pragma unroll
    for (int mi = 0; mi < 4; mi++)
#pragma unroll
        for (int ni = 0; ni < 4; ni++)
#pragma unroll
            for (int r = 0; r < 4; r++) acc[mi][ni][r] = 0.f;

    const int lr = lane >> 2, lc = lane & 3;

#pragma unroll
    for (int k0 = 0; k0 < 64; k0 += 32) {
#pragma unroll
        for (int c = 0; c < 4; c++) {
            float4 a4 = *(const float4*)(Ag + k0 + c * 4);
            float4 b4 = *(const float4*)(Bg + k0 + c * 4);
            float va[4] = {a4.x, a4.y, a4.z, a4.w};
            float vb[4] = {b4.x, b4.y, b4.z, b4.w};
#pragma unroll
            for (int e = 0; e < 4; e++) {
                int k = akb + c * 4 + e;
                int kk = k >> 3, klc = k & 3, kh = (k >> 2) & 1;
                Ap[((a_wm * 4 + kk) * 4 + a_mi) * 132 +
                   (a_lr * 4 + klc) * 4 + a_rh + 2 * kh] = f2tf32(va[e]);
                Bp[((b_wn * 4 + kk) * 4 + b_ni) * 66 +
                   (b_lnr * 4 + klc) * 2 + kh] = f2tf32(vb[e]);
            }
        }
        __syncthreads();
#pragma unroll
        for (int kk = 0; kk < 4; kk++) {
            uint4 af[4]; uint2 bf[4];
#pragma unroll
            for (int mi = 0; mi < 4; mi++)
                af[mi] = *(const uint4*)&Ap[((wm * 4 + kk) * 4 + mi) * 132 + lane * 4];
#pragma unroll
            for (int ni = 0; ni < 4; ni++)
                bf[ni] = *(const uint2*)&Bp[((wn * 4 + kk) * 4 + ni) * 66 + lane * 2];
#pragma unroll
            for (int mi = 0; mi < 4; mi++)
#pragma unroll
                for (int ni = 0; ni < 4; ni++) MMA_TF32(acc[mi][ni], af[mi], bf[ni]);
        }
        __syncthreads();
    }

    float* ob = out + (size_t)bh * QLEN * KLEN;
#pragma unroll
    for (int mi = 0; mi < 4; mi++)
#pragma unroll
        for (int ni = 0; ni < 4; ni++) {
            int row0 = i0 + wm * 64 + mi * 16 + lr;
            int col  = j0 + wn * 32 + ni * 8 + lc * 2;
            *(float2*)(ob + (size_t)row0 * KLEN + col) =
                make_float2(acc[mi][ni][0], acc[mi][ni][1]);
            *(float2*)(ob + (size_t)(row0 + 8) * KLEN + col) =
                make_float2(acc[mi][ni][2], acc[mi][ni][3]);
        }
}

// ---------------- softmax ----------------
__global__ void __launch_bounds__(256) softmax_kernel(float* ac, const float* __restrict__ bd) {
    int i = blockIdx.x;
    int bh = blockIdx.y;
    float* acrow = ac + ((size_t)bh * QLEN + i) * KLEN;
    const float* bdrow = bd + ((size_t)bh * QLEN + i) * KLEN;
    int tid = threadIdx.x;
    __shared__ float red[256];
    int jmax = i + MLEN;
    int shift = QLEN - 1 - i;
    float v[4];
    float m = -1e30f;
#pragma unroll
    for (int c = 0; c < 4; c++) {
        int j = c * 256 + tid;
        float s = (j <= jmax) ? 0.125f * (acrow[j] + bdrow[j + shift]) : -1e30f;
        v[c] = s;
        m = fmaxf(m, s);
    }
    red[tid] = m; __syncthreads();
    for (int o = 128; o > 0; o >>= 1) {
        if (tid < o) red[tid] = fmaxf(red[tid], red[tid + o]);
        __syncthreads();
    }
    m = red[0]; __syncthreads();
    float sum = 0.f;
#pragma unroll
    for (int c = 0; c < 4; c++) { v[c] = expf(v[c] - m); sum += v[c]; }
    red[tid] = sum; __syncthreads();
    for (int o = 128; o > 0; o >>= 1) {
        if (tid < o) red[tid] += red[tid + o];
        __syncthreads();
    }
    float inv = 1.0f / red[0];
#pragma unroll
    for (int c = 0; c < 4; c++) acrow[c * 256 + tid] = v[c] * inv;
}

#define AV_BUF 6336
#define AV_SMEM (2 * AV_BUF * 4)

// ---------------- AV MMA, pipelined (tile 128x64, warp 32x32), epilogue cvt -------
__global__ void __launch_bounds__(256) av_mma(
    const float* __restrict__ P, const float* __restrict__ V, float* __restrict__ av)
{
    extern __shared__ uint32_t dsm[];
    const int by = blockIdx.x, bh = blockIdx.y;
    const int b = bh >> 4, n = bh & 15;
    const float* A = P + (size_t)bh * QLEN * KLEN + (size_t)by * 128 * KLEN;
    const float* Bv = V + (size_t)bh * KLEN * 64;
    const int kmax = min(KLEN, by * 128 + 640);

    const int tid = threadIdx.x, lane = tid & 31, warp = tid >> 5;
    const int wm = warp >> 1, wn = warp & 1;

    const int ar = tid >> 1, akb = (tid & 1) * 16;
    const int a_wm = ar >> 5, a_mi = (ar >> 4) & 1, a_lr = ar & 7, a_rh = (ar >> 3) & 1;
    const float* Ag = A + (size_t)ar * KLEN + akb;

    const int bk = tid & 31, bn0 = (tid >> 5) * 8;
    const int b_kk = bk >> 3, b_lc = bk & 3, b_kh = (bk >> 2) & 1;
    const float* Bg = Bv + (size_t)bk * 64 + bn0;

    float acc[2][4][4];
#pragma unroll
    for (int mi = 0; mi < 2; mi++)
#pragma unroll
        for (int ni = 0; ni < 4; ni++)
#pragma unroll
            for (int r = 0; r < 4; r++) acc[mi][ni][r] = 0.f;

    const int lr = lane >> 2, lc = lane & 3;
    const int niter = kmax >> 5;

    float4 a_st[4], b_st[2];
#define AV_LOAD(k0) do { \
    _Pragma("unroll") for (int c = 0; c < 4; c++) a_st[c] = *(const float4*)(Ag + (k0) + c * 4); \
    _Pragma("unroll") for (int c = 0; c < 2; c++) b_st[c] = *(const float4*)(Bg + (size_t)(k0) * 64 + c * 4); \
} while (0)
#define AV_STS(buf) do { \
    uint32_t* Ap_ = (buf); uint32_t* Bp_ = (buf) + 4224; \
    _Pragma("unroll") for (int c = 0; c < 4; c++) { \
        float va[4] = {a_st[c].x, a_st[c].y, a_st[c].z, a_st[c].w}; \
        _Pragma("unroll") for (int e = 0; e < 4; e++) { \
            int k_ = akb + c * 4 + e; \
            Ap_[((a_wm * 4 + (k_ >> 3)) * 2 + a_mi) * 132 + \
                (a_lr * 4 + (k_ & 3)) * 4 + a_rh + 2 * ((k_ >> 2) & 1)] = f2tf32(va[e]); \
        } \
    } \
    _Pragma("unroll") for (int c = 0; c < 2; c++) { \
        float vb[4] = {b_st[c].x, b_st[c].y, b_st[c].z, b_st[c].w}; \
        _Pragma("unroll") for (int e = 0; e < 4; e++) { \
            int n_ = bn0 + c * 4 + e; \
            Bp_[(((n_ >> 5) * 4 + b_kk) * 4 + ((n_ >> 3) & 3)) * 66 + \
                ((n_ & 7) * 4 + b_lc) * 2 + b_kh] = f2tf32(vb[e]); \
        } \
    } \
} while (0)

    AV_LOAD(0);
    AV_STS(dsm);
    if (niter > 1) AV_LOAD(32);
    __syncthreads();

    for (int it = 0; it < niter; it++) {
        uint32_t* cur = dsm + (it & 1) * AV_BUF;
        if (it + 1 < niter) {
            uint32_t* nxt = dsm + ((it + 1) & 1) * AV_BUF;
            AV_STS(nxt);
        }
        if (it + 2 < niter) AV_LOAD((it + 2) * 32);
        uint32_t* Bpc = cur + 4224;
#pragma unroll
        for (int kk = 0; kk < 4; kk++) {
            uint4 af[2]; uint2 bf[4];
#pragma unroll
            for (int mi = 0; mi < 2; mi++)
                af[mi] = *(const uint4*)&cur[((wm * 4 + kk) * 2 + mi) * 132 + lane * 4];
#pragma unroll
            for (int ni = 0; ni < 4; ni++)
                bf[ni] = *(const uint2*)&Bpc[((wn * 4 + kk) * 4 + ni) * 66 + lane * 2];
#pragma unroll
            for (int mi = 0; mi < 2; mi++)
#pragma unroll
                for (int ni = 0; ni < 4; ni++) MMA_TF32(acc[mi][ni], af[mi], bf[ni]);
        }
        __syncthreads();
    }
#undef AV_LOAD
#undef AV_STS

#pragma unroll
    for (int mi = 0; mi < 2; mi++)
#pragma unroll
        for (int ni = 0; ni < 4; ni++) {
            int row0 = by * 128 + wm * 32 + mi * 16 + lr;
            int col  = wn * 32 + ni * 8 + lc * 2;
            *(float2*)(av + ((size_t)row0 * 4 + b) * 1024 + n * 64 + col) =
                make_float2(f2tf32f(acc[mi][ni][0]), f2tf32f(acc[mi][ni][1]));
            *(float2*)(av + ((size_t)(row0 + 8) * 4 + b) * 1024 + n * 64 + col) =
                make_float2(f2tf32f(acc[mi][ni][2]), f2tf32f(acc[mi][ni][3]));
        }
}

// ---------------- residual add + LayerNorm (output rounded to tf32) ----------------
__global__ void __launch_bounds__(256) add_ln_kernel(
    float* __restrict__ h, const float* __restrict__ t,
    const float* __restrict__ g, const float* __restrict__ b)
{
    int row = blockIdx.x;
    int tid = threadIdx.x;
    __shared__ float rs[256], rs2[256];
    float x[4];
    float s = 0.f, ss = 0.f;
#pragma unroll
    for (int c = 0; c < 4; c++) {
        int d = c * 256 + tid;
        float v = h[(size_t)row * 1024 + d] + t[(size_t)row * 1024 + d];
        x[c] = v; s += v; ss += v * v;
    }
    rs[tid] = s; rs2[tid] = ss; __syncthreads();
    for (int o = 128; o > 0; o >>= 1) {
        if (tid < o) { rs[tid] += rs[tid + o]; rs2[tid] += rs2[tid + o]; }
        __syncthreads();
    }
    float mu = rs[0] * (1.0f / 1024.0f);
    float var = rs2[0] * (1.0f / 1024.0f) - mu * mu;
    float inv = rsqrtf(var + 1e-5f);
#pragma unroll
    for (int c = 0; c < 4; c++) {
        int d = c * 256 + tid;
        h[(size_t)row * 1024 + d] = f2tf32f((x[c] - mu) * inv * g[d] + b[d]);
    }
}

// ---------------- launch ----------------
extern "C" void kernel_launch(void* const* d_in, const int* in_sizes, int n_in,
                              void* d_out, int out_size) {
    (void)in_sizes; (void)n_in; (void)out_size;
    const float* x     = (const float*)d_in[0];
    const float* mems  = (const float*)d_in[1];
    const float* u     = (const float*)d_in[2];
    const float* v     = (const float*)d_in[3];
    const float* W_qkv = (const float*)d_in[4];
    const float* W_o   = (const float*)d_in[5];
    const float* W_r   = (const float*)d_in[6];
    const float* ln1_g = (const float*)d_in[7];
    const float* ln1_b = (const float*)d_in[8];
    const float* W1    = (const float*)d_in[9];
    const float* b1    = (const float*)d_in[10];
    const float* W2    = (const float*)d_in[11];
    const float* b2    = (const float*)d_in[12];
    const float* ln2_g = (const float*)d_in[13];
    const float* ln2_b = (const float*)d_in[14];

    float *cat, *heads, *r, *rk, *ac, *bd, *av, *tmp, *h, *ff, *qu, *qv, *kc, *vc, *rkc;
    cudaGetSymbolAddress((void**)&cat,   g_cat);
    cudaGetSymbolAddress((void**)&heads, g_heads);
    cudaGetSymbolAddress((void**)&r,     g_r);
    cudaGetSymbolAddress((void**)&rk,    g_rk);
    cudaGetSymbolAddress((void**)&ac,    g_ac);
    cudaGetSymbolAddress((void**)&bd,    g_bd);
    cudaGetSymbolAddress((void**)&av,    g_av);
    cudaGetSymbolAddress((void**)&tmp,   g_tmp);
    cudaGetSymbolAddress((void**)&h,     g_h);
    cudaGetSymbolAddress((void**)&ff,    g_ff);
    cudaGetSymbolAddress((void**)&qu,    g_qu);
    cudaGetSymbolAddress((void**)&qv,    g_qv);
    cudaGetSymbolAddress((void**)&kc,    g_kc);
    cudaGetSymbolAddress((void**)&vc,    g_vc);
    cudaGetSymbolAddress((void**)&rkc,   g_rkc);

    cudaFuncSetAttribute(gemm3<0,0,0>, cudaFuncAttributeMaxDynamicSharedMemorySize, GEMM3_SMEM);
    cudaFuncSetAttribute(gemm3<1,1,1>, cudaFuncAttributeMaxDynamicSharedMemorySize, GEMM3_SMEM);
    cudaFuncSetAttribute(gemm3<0,1,0>, cudaFuncAttributeMaxDynamicSharedMemorySize, GEMM3_SMEM);
    cudaFuncSetAttribute(av_mma,       cudaFuncAttributeMaxDynamicSharedMemorySize, AV_SMEM);

    posemb_kernel<<<4096, 256>>>(r);
    copy4_kernel<<<2048, 256>>>((float4*)h, (const float4*)x);

    for (int l = 0; l < NLAYER; l++) {
        const float* Wq = W_qkv + (size_t)l * DMODEL * 3072;
        concat_kernel<<<4096, 256>>>((float4*)cat,
                                     (const float4*)(mems + (size_t)l * MLEN * BATCH * DMODEL),
                                     (const float4*)h);
        // K,V: all 4096 rows, cols 1024..3071
        gemm3<0,0,0><<<dim3(16, 16), 256, GEMM3_SMEM>>>(
            cat, Wq + 1024, nullptr, heads + 1024, 1024, 1024, 3072, 3072);
        // Q: last 2048 rows, cols 0..1023
        gemm3<0,0,0><<<dim3(8, 8), 256, GEMM3_SMEM>>>(
            cat + (size_t)2048 * 1024, Wq, nullptr, heads + (size_t)2048 * 3072,
            1024, 1024, 3072, 3072);
        // rk
        gemm3<0,0,0><<<dim3(8, 4), 256, GEMM3_SMEM>>>(
            r, W_r + (size_t)l * DMODEL * DMODEL, nullptr, rk, 1024, 1024, 1024, 1024);
        // repacks
        repack_quqv<<<2048, 256>>>(heads, u, v, qu, qv);
        repack_kv<<<4096, 256>>>(heads, kc, vc);
        repack_rk<<<1024, 256>>>(rk, rkc);
        // scores
        score_mma<<<dim3(8, 4, BH), 256>>>(qu, kc, ac, 0);
        score_mma<<<dim3(8, 4, BH), 256>>>(qv, rkc, bd, 1);
        softmax_kernel<<<dim3(QLEN, BH), 256>>>(ac, bd);
        av_mma<<<dim3(4, BH), 256, AV_SMEM>>>(ac, vc, av);
        // O projection (A=av pre-rounded in av_mma epilogue)
        gemm3<0,0,0><<<dim3(8, 8), 256, GEMM3_SMEM>>>(
            av, W_o + (size_t)l * DMODEL * DMODEL, nullptr, tmp, 1024, 1024, 1024, 1024);
        add_ln_kernel<<<2048, 256>>>(h, tmp, ln1_g + (size_t)l * DMODEL, ln1_b + (size_t)l * DMODEL);
        // FFN (h pre-rounded by add_ln; ff rounded by FF1 epilogue CVT)
        gemm3<1,1,1><<<dim3(32, 8), 256, GEMM3_SMEM>>>(
            h, W1 + (size_t)l * DMODEL * DINNER, b1 + (size_t)l * DINNER, ff,
            1024, 1024, 4096, 4096);
        gemm3<0,1,0><<<dim3(8, 8), 256, GEMM3_SMEM>>>(
            ff, W2 + (size_t)l * DINNER * DMODEL, b2 + (size_t)l * DMODEL, tmp,
            4096, 4096, 1024, 1024);
        add_ln_kernel<<<2048, 256>>>(h, tmp, ln2_g + (size_t)l * DMODEL, ln2_b + (size_t)l * DMODEL);
    }

    cudaMemcpyAsync(d_out, h, (size_t)QLEN * BATCH * DMODEL * sizeof(float),
                    cudaMemcpyDeviceToDevice);
}

// round 8
// speedup vs baseline: 2.0565x; 1.4783x over previous
#include <cuda_runtime.h>
#include <math.h>
#include <stdint.h>

#define QLEN 512
#define BATCH 4
#define DMODEL 1024
#define NLAYER 4
#define NHEAD 16
#define DHEAD 64
#define DINNER 4096
#define MLEN 512
#define KLEN 1024
#define BH (BATCH*NHEAD)

// ---------------- scratch ----------------
__device__ float g_cat[(size_t)KLEN*BATCH*DMODEL];
__device__ float g_heads[(size_t)KLEN*BATCH*3*DMODEL];
__device__ float g_r[(size_t)KLEN*DMODEL];
__device__ float g_rk[(size_t)KLEN*DMODEL];
__device__ float g_ac[(size_t)BH*QLEN*KLEN];
__device__ float g_bd[(size_t)BH*QLEN*KLEN];
__device__ float g_av[(size_t)QLEN*BATCH*DMODEL];
__device__ float g_tmp[(size_t)QLEN*BATCH*DMODEL];
__device__ float g_h[(size_t)QLEN*BATCH*DMODEL];
__device__ float g_ff[(size_t)QLEN*BATCH*DINNER];
__device__ float g_qu[(size_t)BH*QLEN*DHEAD];
__device__ float g_qv[(size_t)BH*QLEN*DHEAD];
__device__ float g_kc[(size_t)BH*KLEN*DHEAD];
__device__ float g_vc[(size_t)BH*KLEN*DHEAD];
__device__ float g_rkc[(size_t)NHEAD*KLEN*DHEAD];
// tf32-rounded weight copies
__device__ float g_wqkv[(size_t)NLAYER*DMODEL*3072];
__device__ float g_wr[(size_t)NLAYER*DMODEL*DMODEL];
__device__ float g_wo[(size_t)NLAYER*DMODEL*DMODEL];
__device__ float g_w1[(size_t)NLAYER*DMODEL*DINNER];
__device__ float g_w2[(size_t)NLAYER*DINNER*DMODEL];

__device__ __forceinline__ uint32_t f2tf32(float f) {
    uint32_t o;
    asm("cvt.rna.tf32.f32 %0, %1;" : "=r"(o) : "f"(f));
    return o;
}
__device__ __forceinline__ float f2tf32f(float f) {
    uint32_t o = f2tf32(f);
    return __uint_as_float(o);
}

#define MMA_TF32(d, a, b) \
    asm volatile("mma.sync.aligned.m16n8k8.row.col.f32.tf32.tf32.f32 " \
                 "{%0,%1,%2,%3}, {%4,%5,%6,%7}, {%8,%9}, {%0,%1,%2,%3};" \
                 : "+f"(d[0]), "+f"(d[1]), "+f"(d[2]), "+f"(d[3]) \
                 : "r"(a.x), "r"(a.y), "r"(a.z), "r"(a.w), "r"(b.x), "r"(b.y))

__device__ __forceinline__ void cpasync16(uint32_t dst, const void* src) {
    asm volatile("cp.async.cg.shared.global [%0], [%1], 16;" :: "r"(dst), "l"(src));
}
#define CP_COMMIT() asm volatile("cp.async.commit_group;" ::: "memory")
__device__ __forceinline__ uint32_t smem_u32(const void* p) {
    uint32_t a;
    asm("{ .reg .u64 t; cvta.to.shared.u64 t, %1; cvt.u32.u64 %0, t; }" : "=r"(a) : "l"(p));
    return a;
}
#define SW128B(o) ((o) ^ (((o) >> 3) & 0x70))

// gemm4: 3 stages x (A 4096 + B 4096) words
#define G4_STAGE_W 8192
#define G4_SMEM (3 * G4_STAGE_W * 4)

// ======== gemm4: C[M,N]=A[M,K]@B[K,N]. 128 thr, CTA 128x128, warp 64x64 ========
// A and B both pre-rounded tf32; both streamed via cp.async.
template<int RELU, int HASBIAS, int CVT>
__global__ void __launch_bounds__(128) gemm4(
    const float* __restrict__ A, const float* __restrict__ B,
    const float* __restrict__ bias, float* __restrict__ C,
    int K, int lda, int ldb, int ldc)
{
    extern __shared__ uint32_t dsm[];
    const uint32_t sbase = smem_u32(dsm);
    const int tid = threadIdx.x, lane = tid & 31;
    const int warp = tid >> 5, wm = warp >> 1, wn = warp & 1;
    const int bx = blockIdx.x, by = blockIdx.y;

    // A: 128 rows x 32 floats per stage; thread -> rows (tid>>3)+16i, chunk tid&7
    const int a_row0 = tid >> 3, a_ch = tid & 7;
    const float* Ag = A + (size_t)(by * 128 + a_row0) * lda + a_ch * 4;
    // B: 32 k-rows x 128 floats; thread -> k = tid>>2, n-chunks (tid&3)+4i
    const int b_k = tid >> 2, b_nch0 = tid & 3;
    const float* Bg = B + (size_t)b_k * ldb + bx * 128 + b_nch0 * 4;

    float acc[4][8][4];
#pragma unroll
    for (int mi = 0; mi < 4; mi++)
#pragma unroll
        for (int ni = 0; ni < 8; ni++)
#pragma unroll
            for (int r = 0; r < 4; r++) acc[mi][ni][r] = 0.f;

    const int lr = lane >> 2, lc = lane & 3;
    const int niter = K >> 5;

#define G4_LOAD(stg, k0) do { \
    uint32_t ab_ = sbase + (stg) * (G4_STAGE_W * 4); \
    _Pragma("unroll") for (int i = 0; i < 8; i++) { \
        uint32_t so_ = SW128B((uint32_t)((a_row0 + 16 * i) * 128 + a_ch * 16)); \
        cpasync16(ab_ + so_, Ag + (size_t)(16 * i) * lda + (k0)); \
    } \
    uint32_t bb_ = ab_ + 4096 * 4; \
    _Pragma("unroll") for (int i = 0; i < 8; i++) { \
        int n_ = (b_nch0 + 4 * i) * 4; \
        uint32_t w_ = (uint32_t)(b_k * 128 + (n_ ^ ((b_k & 3) << 3))); \
        cpasync16(bb_ + w_ * 4, Bg + (size_t)(k0) * ldb + 16 * i); \
    } \
    CP_COMMIT(); \
} while (0)

    G4_LOAD(0, 0);
    if (niter > 1) G4_LOAD(1, 32);

    for (int it = 0; it < niter; it++) {
        if (it + 1 < niter) {
            asm volatile("cp.async.wait_group 1;" ::: "memory");
        } else {
            asm volatile("cp.async.wait_group 0;" ::: "memory");
        }
        __syncthreads();
        if (it + 2 < niter) G4_LOAD((it + 2) % 3, (it + 2) * 32);

        const uint32_t* Abuf = dsm + (it % 3) * G4_STAGE_W;
        const uint32_t* Bbuf = Abuf + 4096;
#pragma unroll
        for (int kk = 0; kk < 4; kk++) {
            uint4 af[4]; uint2 bf[8];
#pragma unroll
            for (int mi = 0; mi < 4; mi++) {
                int row = wm * 64 + mi * 16 + lr;
                int k = kk * 8 + lc;
                af[mi].x = Abuf[SW128B((uint32_t)(row * 128 + k * 4)) >> 2];
                af[mi].y = Abuf[SW128B((uint32_t)((row + 8) * 128 + k * 4)) >> 2];
                af[mi].z = Abuf[SW128B((uint32_t)(row * 128 + (k + 4) * 4)) >> 2];
                af[mi].w = Abuf[SW128B((uint32_t)((row + 8) * 128 + (k + 4) * 4)) >> 2];
            }
#pragma unroll
            for (int ni = 0; ni < 8; ni++) {
                int n = wn * 64 + ni * 8 + lr;
                int kb = kk * 8 + lc;
                int nsw = n ^ (lc << 3);
                bf[ni].x = Bbuf[kb * 128 + nsw];
                bf[ni].y = Bbuf[(kb + 4) * 128 + nsw];
            }
#pragma unroll
            for (int mi = 0; mi < 4; mi++)
#pragma unroll
                for (int ni = 0; ni < 8; ni++) MMA_TF32(acc[mi][ni], af[mi], bf[ni]);
        }
    }
#undef G4_LOAD

#pragma unroll
    for (int mi = 0; mi < 4; mi++) {
#pragma unroll
        for (int ni = 0; ni < 8; ni++) {
            int row0 = by * 128 + wm * 64 + mi * 16 + lr;
            int col  = bx * 128 + wn * 64 + ni * 8 + lc * 2;
            float b0 = 0.f, b1 = 0.f;
            if (HASBIAS) { b0 = bias[col]; b1 = bias[col + 1]; }
            float v0 = acc[mi][ni][0] + b0, v1 = acc[mi][ni][1] + b1;
            float v2 = acc[mi][ni][2] + b0, v3 = acc[mi][ni][3] + b1;
            if (RELU) {
                v0 = fmaxf(v0, 0.f); v1 = fmaxf(v1, 0.f);
                v2 = fmaxf(v2, 0.f); v3 = fmaxf(v3, 0.f);
            }
            if (CVT) {
                v0 = f2tf32f(v0); v1 = f2tf32f(v1);
                v2 = f2tf32f(v2); v3 = f2tf32f(v3);
            }
            *(float2*)(C + (size_t)row0 * ldc + col)       = make_float2(v0, v1);
            *(float2*)(C + (size_t)(row0 + 8) * ldc + col) = make_float2(v2, v3);
        }
    }
}

// ---------------- weight rounding (once per call) ----------------
__global__ void roundw_kernel(float4* __restrict__ dst, const float4* __restrict__ src) {
    size_t i = (size_t)blockIdx.x * 256 + threadIdx.x;
    float4 v = src[i];
    dst[i] = make_float4(f2tf32f(v.x), f2tf32f(v.y), f2tf32f(v.z), f2tf32f(v.w));
}

// ---------------- small kernels ----------------
__global__ void posemb_kernel(float* __restrict__ r) {
    int idx = blockIdx.x * 256 + threadIdx.x;
    int k = idx >> 10, d = idx & 1023;
    float pos = (float)(KLEN - 1 - k);
    int j = (d < 512) ? d : d - 512;
    float inv = expf(-((float)(2 * j) / 1024.0f) * 9.210340371976184f);
    float ang = pos * inv;
    r[idx] = f2tf32f((d < 512) ? sinf(ang) : cosf(ang));
}

__global__ void copy4_kernel(float4* __restrict__ dst, const float4* __restrict__ src) {
    size_t i = (size_t)blockIdx.x * 256 + threadIdx.x;
    dst[i] = src[i];
}

__global__ void concat_kernel(float4* __restrict__ cat, const float4* __restrict__ mem,
                              const float4* __restrict__ h) {
    size_t i = (size_t)blockIdx.x * 256 + threadIdx.x;
    const size_t half = (size_t)MLEN * BATCH * DMODEL / 4;
    float4 v = (i < half) ? mem[i] : h[i - half];
    cat[i] = make_float4(f2tf32f(v.x), f2tf32f(v.y), f2tf32f(v.z), f2tf32f(v.w));
}

__global__ void repack_quqv(const float* __restrict__ heads, const float* __restrict__ u,
                            const float* __restrict__ v, float* __restrict__ qu,
                            float* __restrict__ qv) {
    int idx = blockIdx.x * 256 + threadIdx.x;
    int d4 = idx & 15, i = (idx >> 4) & 511, bh = idx >> 13;
    int b = bh >> 4, n = bh & 15;
    float4 q = *(const float4*)(heads + ((size_t)((512 + i) * 4 + b)) * 3072 + n * 64 + d4 * 4);
    float4 uu = *(const float4*)(u + n * 64 + d4 * 4);
    float4 vv = *(const float4*)(v + n * 64 + d4 * 4);
    size_t o = ((size_t)bh * 512 + i) * 64 + d4 * 4;
    *(float4*)(qu + o) = make_float4(q.x + uu.x, q.y + uu.y, q.z + uu.z, q.w + uu.w);
    *(float4*)(qv + o) = make_float4(q.x + vv.x, q.y + vv.y, q.z + vv.z, q.w + vv.w);
}

__global__ void repack_kv(const float* __restrict__ heads, float* __restrict__ kc,
                          float* __restrict__ vc) {
    int idx = blockIdx.x * 256 + threadIdx.x;
    int d4 = idx & 15, j = (idx >> 4) & 1023, bh = idx >> 14;
    int b = bh >> 4, n = bh & 15;
    const float* base = heads + ((size_t)(j * 4 + b)) * 3072 + n * 64 + d4 * 4;
    float4 kx = *(const float4*)(base + 1024);
    float4 vx = *(const float4*)(base + 2048);
    size_t o = ((size_t)bh * 1024 + j) * 64 + d4 * 4;
    *(float4*)(kc + o) = kx;
    *(float4*)(vc + o) = vx;
}

__global__ void repack_rk(const float* __restrict__ rk, float* __restrict__ rkc) {
    int idx = blockIdx.x * 256 + threadIdx.x;
    int d4 = idx & 15, j = (idx >> 4) & 1023, n = idx >> 14;
    *(float4*)(rkc + ((size_t)n * 1024 + j) * 64 + d4 * 4) =
        *(const float4*)(rk + (size_t)j * 1024 + n * 64 + d4 * 4);
}

// ---------------- score MMA (A @ B^T, K=64) ----------------
__global__ void __launch_bounds__(256, 2) score_mma(
    const float* __restrict__ Qb, const float* __restrict__ Kb,
    float* __restrict__ out, int mode)
{
    const int bx = blockIdx.x, by = blockIdx.y, bh = blockIdx.z;
    const int i0 = by * 128, j0 = bx * 128;
    if (mode == 0) { if (j0 >= i0 + 640) return; }
    else           { if (i0 + j0 < 257) return; }
    const float* A = Qb + (size_t)bh * QLEN * 64;
    const float* B = Kb + (size_t)(mode ? (bh & 15) : bh) * KLEN * 64;

    __shared__ uint32_t Ap[4224];
    __shared__ uint32_t Bp[4224];
    const int tid = threadIdx.x, lane = tid & 31;
    const int warp = tid >> 5, wm = warp >> 2, wn = warp & 3;

    const int ar = tid >> 1, akb = (tid & 1) * 16;
    const int a_wm = ar >> 6, a_mi = (ar >> 4) & 3, a_lr = ar & 7, a_rh = (ar >> 3) & 1;
    const float* Ag = A + (size_t)(i0 + ar) * 64 + akb;
    const float* Bg = B + (size_t)(j0 + ar) * 64 + akb;
    const int b_wn = ar >> 5, b_ni = (ar >> 3) & 3, b_lnr = ar & 7;

    float acc[4][4][4];
#pragma unroll
    for (int mi = 0; mi < 4; mi++)
#pragma unroll
        for (int ni = 0; ni < 4; ni++)
#pragma unroll
            for (int r = 0; r < 4; r++) acc[mi][ni][r] = 0.f;

    const int lr = lane >> 2, lc = lane & 3;

#pragma unroll
    for (int k0 = 0; k0 < 64; k0 += 32) {
#pragma unroll
        for (int c = 0; c < 4; c++) {
            float4 a4 = *(const float4*)(Ag + k0 + c * 4);
            float4 b4 = *(const float4*)(Bg + k0 + c * 4);
            float va[4] = {a4.x, a4.y, a4.z, a4.w};
            float vb[4] = {b4.x, b4.y, b4.z, b4.w};
#pragma unroll
            for (int e = 0; e < 4; e++) {
                int k = akb + c * 4 + e;
                int kk = k >> 3, klc = k & 3, kh = (k >> 2) & 1;
                Ap[((a_wm * 4 + kk) * 4 + a_mi) * 132 +
                   (a_lr * 4 + klc) * 4 + a_rh + 2 * kh] = f2tf32(va[e]);
                Bp[((b_wn * 4 + kk) * 4 + b_ni) * 66 +
                   (b_lnr * 4 + klc) * 2 + kh] = f2tf32(vb[e]);
            }
        }
        __syncthreads();
#pragma unroll
        for (int kk = 0; kk < 4; kk++) {
            uint4 af[4]; uint2 bf[4];
#pragma unroll
            for (int mi = 0; mi < 4; mi++)
                af[mi] = *(const uint4*)&Ap[((wm * 4 + kk) * 4 + mi) * 132 + lane * 4];
#pragma unroll
            for (int ni = 0; ni < 4; ni++)
                bf[ni] = *(const uint2*)&Bp[((wn * 4 + kk) * 4 + ni) * 66 + lane * 2];
#pragma unroll
            for (int mi = 0; mi < 4; mi++)
#pragma unroll
                for (int ni = 0; ni < 4; ni++) MMA_TF32(acc[mi][ni], af[mi], bf[ni]);
        }
        __syncthreads();
    }

    float* ob = out + (size_t)bh * QLEN * KLEN;
#pragma unroll
    for (int mi = 0; mi < 4; mi++)
#pragma unroll
        for (int ni = 0; ni < 4; ni++) {
            int row0 = i0 + wm * 64 + mi * 16 + lr;
            int col  = j0 + wn * 32 + ni * 8 + lc * 2;
            *(float2*)(ob + (size_t)row0 * KLEN + col) =
                make_float2(acc[mi][ni][0], acc[mi][ni][1]);
            *(float2*)(ob + (size_t)(row0 + 8) * KLEN + col) =
                make_float2(acc[mi][ni][2], acc[mi][ni][3]);
        }
}

// ---------------- softmax ----------------
__global__ void __launch_bounds__(256) softmax_kernel(float* ac, const float* __restrict__ bd) {
    int i = blockIdx.x;
    int bh = blockIdx.y;
    float* acrow = ac + ((size_t)bh * QLEN + i) * KLEN;
    const float* bdrow = bd + ((size_t)bh * QLEN + i) * KLEN;
    int tid = threadIdx.x;
    __shared__ float red[256];
    int jmax = i + MLEN;
    int shift = QLEN - 1 - i;
    float v[4];
    float m = -1e30f;
#pragma unroll
    for (int c = 0; c < 4; c++) {
        int j = c * 256 + tid;
        float s = (j <= jmax) ? 0.125f * (acrow[j] + bdrow[j + shift]) : -1e30f;
        v[c] = s;
        m = fmaxf(m, s);
    }
    red[tid] = m; __syncthreads();
    for (int o = 128; o > 0; o >>= 1) {
        if (tid < o) red[tid] = fmaxf(red[tid], red[tid + o]);
        __syncthreads();
    }
    m = red[0]; __syncthreads();
    float sum = 0.f;
#pragma unroll
    for (int c = 0; c < 4; c++) { v[c] = expf(v[c] - m); sum += v[c]; }
    red[tid] = sum; __syncthreads();
    for (int o = 128; o > 0; o >>= 1) {
        if (tid < o) red[tid] += red[tid + o];
        __syncthreads();
    }
    float inv = 1.0f / red[0];
#pragma unroll
    for (int c = 0; c < 4; c++) acrow[c * 256 + tid] = v[c] * inv;
}

#define AV_BUF 6336
#define AV_SMEM (2 * AV_BUF * 4)

// ---------------- AV MMA, pipelined (tile 128x64, warp 32x32), epilogue cvt -------
__global__ void __launch_bounds__(256) av_mma(
    const float* __restrict__ P, const float* __restrict__ V, float* __restrict__ av)
{
    extern __shared__ uint32_t dsm[];
    const int by = blockIdx.x, bh = blockIdx.y;
    const int b = bh >> 4, n = bh & 15;
    const float* A = P + (size_t)bh * QLEN * KLEN + (size_t)by * 128 * KLEN;
    const float* Bv = V + (size_t)bh * KLEN * 64;
    const int kmax = min(KLEN, by * 128 + 640);

    const int tid = threadIdx.x, lane = tid & 31, warp = tid >> 5;
    const int wm = warp >> 1, wn = warp & 1;

    const int ar = tid >> 1, akb = (tid & 1) * 16;
    const int a_wm = ar >> 5, a_mi = (ar >> 4) & 1, a_lr = ar & 7, a_rh = (ar >> 3) & 1;
    const float* Ag = A + (size_t)ar * KLEN + akb;

    const int bk = tid & 31, bn0 = (tid >> 5) * 8;
    const int b_kk = bk >> 3, b_lc = bk & 3, b_kh = (bk >> 2) & 1;
    const float* Bg = Bv + (size_t)bk * 64 + bn0;

    float acc[2][4][4];
#pragma unroll
    for (int mi = 0; mi < 2; mi++)
#pragma unroll
        for (int ni = 0; ni < 4; ni++)
#pragma unroll
            for (int r = 0; r < 4; r++) acc[mi][ni][r] = 0.f;

    const int lr = lane >> 2, lc = lane & 3;
    const int niter = kmax >> 5;

    float4 a_st[4], b_st[2];
#define AV_LOAD(k0) do { \
    _Pragma("unroll") for (int c = 0; c < 4; c++) a_st[c] = *(const float4*)(Ag + (k0) + c * 4); \
    _Pragma("unroll") for (int c = 0; c < 2; c++) b_st[c] = *(const float4*)(Bg + (size_t)(k0) * 64 + c * 4); \
} while (0)
#define AV_STS(buf) do { \
    uint32_t* Ap_ = (buf); uint32_t* Bp_ = (buf) + 4224; \
    _Pragma("unroll") for (int c = 0; c < 4; c++) { \
        float va[4] = {a_st[c].x, a_st[c].y, a_st[c].z, a_st[c].w}; \
        _Pragma("unroll") for (int e = 0; e < 4; e++) { \
            int k_ = akb + c * 4 + e; \
            Ap_[((a_wm * 4 + (k_ >> 3)) * 2 + a_mi) * 132 + \
                (a_lr * 4 + (k_ & 3)) * 4 + a_rh + 2 * ((k_ >> 2) & 1)] = f2tf32(va[e]); \
        } \
    } \
    _Pragma("unroll") for (int c = 0; c < 2; c++) { \
        float vb[4] = {b_st[c].x, b_st[c].y, b_st[c].z, b_st[c].w}; \
        _Pragma("unroll") for (int e = 0; e < 4; e++) { \
            int n_ = bn0 + c * 4 + e; \
            Bp_[(((n_ >> 5) * 4 + b_kk) * 4 + ((n_ >> 3) & 3)) * 66 + \
                ((n_ & 7) * 4 + b_lc) * 2 + b_kh] = f2tf32(vb[e]); \
        } \
    } \
} while (0)

    AV_LOAD(0);
    AV_STS(dsm);
    if (niter > 1) AV_LOAD(32);
    __syncthreads();

    for (int it = 0; it < niter; it++) {
        uint32_t* cur = dsm + (it & 1) * AV_BUF;
        if (it + 1 < niter) {
            uint32_t* nxt = dsm + ((it + 1) & 1) * AV_BUF;
            AV_STS(nxt);
        }
        if (it + 2 < niter) AV_LOAD((it + 2) * 32);
        uint32_t* Bpc = cur + 4224;
#pragma unroll
        for (int kk = 0; kk < 4; kk++) {
            uint4 af[2]; uint2 bf[4];
#pragma unroll
            for (int mi = 0; mi < 2; mi++)
                af[mi] = *(const uint4*)&cur[((wm * 4 + kk) * 2 + mi) * 132 + lane * 4];
#pragma unroll
            for (int ni = 0; ni < 4; ni++)
                bf[ni] = *(const uint2*)&Bpc[((wn * 4 + kk) * 4 + ni) * 66 + lane * 2];
#pragma unroll
            for (int mi = 0; mi < 2; mi++)
#pragma unroll
                for (int ni = 0; ni < 4; ni++) MMA_TF32(acc[mi][ni], af[mi], bf[ni]);
        }
        __syncthreads();
    }
#undef AV_LOAD
#undef AV_STS

#pragma unroll
    for (int mi = 0; mi < 2; mi++)
#pragma unroll
        for (int ni = 0; ni < 4; ni++) {
            int row0 = by * 128 + wm * 32 + mi * 16 + lr;
            int col  = wn * 32 + ni * 8 + lc * 2;
            *(float2*)(av + ((size_t)row0 * 4 + b) * 1024 + n * 64 + col) =
                make_float2(f2tf32f(acc[mi][ni][0]), f2tf32f(acc[mi][ni][1]));
            *(float2*)(av + ((size_t)(row0 + 8) * 4 + b) * 1024 + n * 64 + col) =
                make_float2(f2tf32f(acc[mi][ni][2]), f2tf32f(acc[mi][ni][3]));
        }
}

// ---------------- residual add + LayerNorm (output rounded to tf32) ----------------
__global__ void __launch_bounds__(256) add_ln_kernel(
    float* __restrict__ h, const float* __restrict__ t,
    const float* __restrict__ g, const float* __restrict__ b)
{
    int row = blockIdx.x;
    int tid = threadIdx.x;
    __shared__ float rs[256], rs2[256];
    float x[4];
    float s = 0.f, ss = 0.f;
#pragma unroll
    for (int c = 0; c < 4; c++) {
        int d = c * 256 + tid;
        float v = h[(size_t)row * 1024 + d] + t[(size_t)row * 1024 + d];
        x[c] = v; s += v; ss += v * v;
    }
    rs[tid] = s; rs2[tid] = ss; __syncthreads();
    for (int o = 128; o > 0; o >>= 1) {
        if (tid < o) { rs[tid] += rs[tid + o]; rs2[tid] += rs2[tid + o]; }
        __syncthreads();
    }
    float mu = rs[0] * (1.0f / 1024.0f);
    float var = rs2[0] * (1.0f / 1024.0f) - mu * mu;
    float inv = rsqrtf(var + 1e-5f);
#pragma unroll
    for (int c = 0; c < 4; c++) {
        int d = c * 256 + tid;
        h[(size_t)row * 1024 + d] = f2tf32f((x[c] - mu) * inv * g[d] + b[d]);
    }
}

// ---------------- launch ----------------
extern "C" void kernel_launch(void* const* d_in, const int* in_sizes, int n_in,
                              void* d_out, int out_size) {
    (void)in_sizes; (void)n_in; (void)out_size;
    const float* x     = (const float*)d_in[0];
    const float* mems  = (const float*)d_in[1];
    const float* u     = (const float*)d_in[2];
    const float* v     = (const float*)d_in[3];
    const float* W_qkv = (const float*)d_in[4];
    const float* W_o   = (const float*)d_in[5];
    const float* W_r   = (const float*)d_in[6];
    const float* ln1_g = (const float*)d_in[7];
    const float* ln1_b = (const float*)d_in[8];
    const float* W1    = (const float*)d_in[9];
    const float* b1    = (const float*)d_in[10];
    const float* W2    = (const float*)d_in[11];
    const float* b2    = (const float*)d_in[12];
    const float* ln2_g = (const float*)d_in[13];
    const float* ln2_b = (const float*)d_in[14];

    float *cat, *heads, *r, *rk, *ac, *bd, *av, *tmp, *h, *ff, *qu, *qv, *kc, *vc, *rkc;
    float *wqkv, *wr, *wo, *w1, *w2;
    cudaGetSymbolAddress((void**)&cat,   g_cat);
    cudaGetSymbolAddress((void**)&heads, g_heads);
    cudaGetSymbolAddress((void**)&r,     g_r);
    cudaGetSymbolAddress((void**)&rk,    g_rk);
    cudaGetSymbolAddress((void**)&ac,    g_ac);
    cudaGetSymbolAddress((void**)&bd,    g_bd);
    cudaGetSymbolAddress((void**)&av,    g_av);
    cudaGetSymbolAddress((void**)&tmp,   g_tmp);
    cudaGetSymbolAddress((void**)&h,     g_h);
    cudaGetSymbolAddress((void**)&ff,    g_ff);
    cudaGetSymbolAddress((void**)&qu,    g_qu);
    cudaGetSymbolAddress((void**)&qv,    g_qv);
    cudaGetSymbolAddress((void**)&kc,    g_kc);
    cudaGetSymbolAddress((void**)&vc,    g_vc);
    cudaGetSymbolAddress((void**)&rkc,   g_rkc);
    cudaGetSymbolAddress((void**)&wqkv,  g_wqkv);
    cudaGetSymbolAddress((void**)&wr,    g_wr);
    cudaGetSymbolAddress((void**)&wo,    g_wo);
    cudaGetSymbolAddress((void**)&w1,    g_w1);
    cudaGetSymbolAddress((void**)&w2,    g_w2);

    cudaFuncSetAttribute(gemm4<0,0,0>, cudaFuncAttributeMaxDynamicSharedMemorySize, G4_SMEM);
    cudaFuncSetAttribute(gemm4<1,1,1>, cudaFuncAttributeMaxDynamicSharedMemorySize, G4_SMEM);
    cudaFuncSetAttribute(gemm4<0,1,0>, cudaFuncAttributeMaxDynamicSharedMemorySize, G4_SMEM);
    cudaFuncSetAttribute(av_mma,       cudaFuncAttributeMaxDynamicSharedMemorySize, AV_SMEM);

    // one-time weight rounding (graph-capturable, deterministic)
    roundw_kernel<<<(NLAYER*DMODEL*3072/4)/256, 256>>>((float4*)wqkv, (const float4*)W_qkv);
    roundw_kernel<<<(NLAYER*DMODEL*DMODEL/4)/256, 256>>>((float4*)wr, (const float4*)W_r);
    roundw_kernel<<<(NLAYER*DMODEL*DMODEL/4)/256, 256>>>((float4*)wo, (const float4*)W_o);
    roundw_kernel<<<(NLAYER*DMODEL*DINNER/4)/256, 256>>>((float4*)w1, (const float4*)W1);
    roundw_kernel<<<(NLAYER*DINNER*DMODEL/4)/256, 256>>>((float4*)w2, (const float4*)W2);

    posemb_kernel<<<4096, 256>>>(r);
    copy4_kernel<<<2048, 256>>>((float4*)h, (const float4*)x);

    for (int l = 0; l < NLAYER; l++) {
        const float* Wq = wqkv + (size_t)l * DMODEL * 3072;
        concat_kernel<<<4096, 256>>>((float4*)cat,
                                     (const float4*)(mems + (size_t)l * MLEN * BATCH * DMODEL),
                                     (const float4*)h);
        // K,V: all 4096 rows, cols 1024..3071
        gemm4<0,0,0><<<dim3(16, 32), 128, G4_SMEM>>>(
            cat, Wq + 1024, nullptr, heads + 1024, 1024, 1024, 3072, 3072);
        // Q: last 2048 rows, cols 0..1023
        gemm4<0,0,0><<<dim3(8, 16), 128, G4_SMEM>>>(
            cat + (size_t)2048 * 1024, Wq, nullptr, heads + (size_t)2048 * 3072,
            1024, 1024, 3072, 3072);
        // rk
        gemm4<0,0,0><<<dim3(8, 8), 128, G4_SMEM>>>(
            r, wr + (size_t)l * DMODEL * DMODEL, nullptr, rk, 1024, 1024, 1024, 1024);
        // repacks
        repack_quqv<<<2048, 256>>>(heads, u, v, qu, qv);
        repack_kv<<<4096, 256>>>(heads, kc, vc);
        repack_rk<<<1024, 256>>>(rk, rkc);
        // scores
        score_mma<<<dim3(8, 4, BH), 256>>>(qu, kc, ac, 0);
        score_mma<<<dim3(8, 4, BH), 256>>>(qv, rkc, bd, 1);
        softmax_kernel<<<dim3(QLEN, BH), 256>>>(ac, bd);
        av_mma<<<dim3(4, BH), 256, AV_SMEM>>>(ac, vc, av);
        // O projection
        gemm4<0,0,0><<<dim3(8, 16), 128, G4_SMEM>>>(
            av, wo + (size_t)l * DMODEL * DMODEL, nullptr, tmp, 1024, 1024, 1024, 1024);
        add_ln_kernel<<<2048, 256>>>(h, tmp, ln1_g + (size_t)l * DMODEL, ln1_b + (size_t)l * DMODEL);
        // FFN
        gemm4<1,1,1><<<dim3(32, 16), 128, G4_SMEM>>>(
            h, w1 + (size_t)l * DMODEL * DINNER, b1 + (size_t)l * DINNER, ff,
            1024, 1024, 4096, 4096);
        gemm4<0,1,0><<<dim3(8, 16), 128, G4_SMEM>>>(
            ff, w2 + (size_t)l * DINNER * DMODEL, b2 + (size_t)l * DMODEL, tmp,
            4096, 4096, 1024, 1024);
        add_ln_kernel<<<2048, 256>>>(h, tmp, ln2_g + (size_t)l * DMODEL, ln2_b + (size_t)l * DMODEL);
    }

    cudaMemcpyAsync(d_out, h, (size_t)QLEN * BATCH * DMODEL * sizeof(float),
                    cudaMemcpyDeviceToDevice);
}

// round 9
// speedup vs baseline: 2.3938x; 1.1640x over previous
#include <cuda_runtime.h>
#include <math.h>
#include <stdint.h>

#define QLEN 512
#define BATCH 4
#define DMODEL 1024
#define NLAYER 4
#define NHEAD 16
#define DHEAD 64
#define DINNER 4096
#define MLEN 512
#define KLEN 1024
#define BH (BATCH*NHEAD)

// ---------------- scratch ----------------
__device__ float g_cat[(size_t)KLEN*BATCH*DMODEL];
__device__ float g_heads[(size_t)KLEN*BATCH*3*DMODEL];
__device__ float g_r[(size_t)KLEN*DMODEL];
__device__ float g_rk[(size_t)KLEN*DMODEL];
__device__ float g_ac[(size_t)BH*QLEN*KLEN];
__device__ float g_bd[(size_t)BH*QLEN*KLEN];
__device__ float g_av[(size_t)QLEN*BATCH*DMODEL];
__device__ float g_tmp[(size_t)QLEN*BATCH*DMODEL];
__device__ float g_h[(size_t)QLEN*BATCH*DMODEL];
__device__ float g_ff[(size_t)QLEN*BATCH*DINNER];
__device__ float g_qu[(size_t)BH*QLEN*DHEAD];
__device__ float g_qv[(size_t)BH*QLEN*DHEAD];
__device__ float g_kc[(size_t)BH*KLEN*DHEAD];
__device__ float g_vc[(size_t)BH*KLEN*DHEAD];
__device__ float g_rkc[(size_t)NHEAD*KLEN*DHEAD];
// tf32-rounded weight copies
__device__ float g_wqkv[(size_t)NLAYER*DMODEL*3072];
__device__ float g_wr[(size_t)NLAYER*DMODEL*DMODEL];
__device__ float g_wo[(size_t)NLAYER*DMODEL*DMODEL];
__device__ float g_w1[(size_t)NLAYER*DMODEL*DINNER];
__device__ float g_w2[(size_t)NLAYER*DINNER*DMODEL];

__device__ __forceinline__ uint32_t f2tf32(float f) {
    uint32_t o;
    asm("cvt.rna.tf32.f32 %0, %1;" : "=r"(o) : "f"(f));
    return o;
}
__device__ __forceinline__ float f2tf32f(float f) {
    uint32_t o = f2tf32(f);
    return __uint_as_float(o);
}

#define MMA_TF32(d, a, b) \
    asm volatile("mma.sync.aligned.m16n8k8.row.col.f32.tf32.tf32.f32 " \
                 "{%0,%1,%2,%3}, {%4,%5,%6,%7}, {%8,%9}, {%0,%1,%2,%3};" \
                 : "+f"(d[0]), "+f"(d[1]), "+f"(d[2]), "+f"(d[3]) \
                 : "r"(a.x), "r"(a.y), "r"(a.z), "r"(a.w), "r"(b.x), "r"(b.y))

__device__ __forceinline__ void cpasync16(uint32_t dst, const void* src) {
    asm volatile("cp.async.cg.shared.global [%0], [%1], 16;" :: "r"(dst), "l"(src));
}
#define CP_COMMIT() asm volatile("cp.async.commit_group;" ::: "memory")
__device__ __forceinline__ uint32_t smem_u32(const void* p) {
    uint32_t a;
    asm("{ .reg .u64 t; cvta.to.shared.u64 t, %1; cvt.u32.u64 %0, t; }" : "=r"(a) : "l"(p));
    return a;
}
#define SW128B(o) ((o) ^ (((o) >> 3) & 0x70))

// gemm4: 3 stages x (A 4096 + B 4096) words
#define G4_STAGE_W 8192
#define G4_SMEM (3 * G4_STAGE_W * 4)

// ======== gemm4: C[M,N]=A[M,K]@B[K,N]. 128 thr, CTA 128x128, warp 64x64 ========
template<int RELU, int HASBIAS, int CVT>
__global__ void __launch_bounds__(128) gemm4(
    const float* __restrict__ A, const float* __restrict__ B,
    const float* __restrict__ bias, float* __restrict__ C,
    int K, int lda, int ldb, int ldc)
{
    extern __shared__ uint32_t dsm[];
    const uint32_t sbase = smem_u32(dsm);
    const int tid = threadIdx.x, lane = tid & 31;
    const int warp = tid >> 5, wm = warp >> 1, wn = warp & 1;
    const int bx = blockIdx.x, by = blockIdx.y;

    const int a_row0 = tid >> 3, a_ch = tid & 7;
    const float* Ag = A + (size_t)(by * 128 + a_row0) * lda + a_ch * 4;
    const int b_k = tid >> 2, b_nch0 = tid & 3;
    const float* Bg = B + (size_t)b_k * ldb + bx * 128 + b_nch0 * 4;

    float acc[4][8][4];
#pragma unroll
    for (int mi = 0; mi < 4; mi++)
#pragma unroll
        for (int ni = 0; ni < 8; ni++)
#pragma unroll
            for (int r = 0; r < 4; r++) acc[mi][ni][r] = 0.f;

    const int lr = lane >> 2, lc = lane & 3;
    const int niter = K >> 5;

#define G4_LOAD(stg, k0) do { \
    uint32_t ab_ = sbase + (stg) * (G4_STAGE_W * 4); \
    _Pragma("unroll") for (int i = 0; i < 8; i++) { \
        uint32_t so_ = SW128B((uint32_t)((a_row0 + 16 * i) * 128 + a_ch * 16)); \
        cpasync16(ab_ + so_, Ag + (size_t)(16 * i) * lda + (k0)); \
    } \
    uint32_t bb_ = ab_ + 4096 * 4; \
    _Pragma("unroll") for (int i = 0; i < 8; i++) { \
        int n_ = (b_nch0 + 4 * i) * 4; \
        uint32_t w_ = (uint32_t)(b_k * 128 + (n_ ^ ((b_k & 3) << 3))); \
        cpasync16(bb_ + w_ * 4, Bg + (size_t)(k0) * ldb + 16 * i); \
    } \
    CP_COMMIT(); \
} while (0)

    G4_LOAD(0, 0);
    if (niter > 1) G4_LOAD(1, 32);

    for (int it = 0; it < niter; it++) {
        if (it + 1 < niter) {
            asm volatile("cp.async.wait_group 1;" ::: "memory");
        } else {
            asm volatile("cp.async.wait_group 0;" ::: "memory");
        }
        __syncthreads();
        if (it + 2 < niter) G4_LOAD((it + 2) % 3, (it + 2) * 32);

        const uint32_t* Abuf = dsm + (it % 3) * G4_STAGE_W;
        const uint32_t* Bbuf = Abuf + 4096;
#pragma unroll
        for (int kk = 0; kk < 4; kk++) {
            uint4 af[4]; uint2 bf[8];
#pragma unroll
            for (int mi = 0; mi < 4; mi++) {
                int row = wm * 64 + mi * 16 + lr;
                int k = kk * 8 + lc;
                af[mi].x = Abuf[SW128B((uint32_t)(row * 128 + k * 4)) >> 2];
                af[mi].y = Abuf[SW128B((uint32_t)((row + 8) * 128 + k * 4)) >> 2];
                af[mi].z = Abuf[SW128B((uint32_t)(row * 128 + (k + 4) * 4)) >> 2];
                af[mi].w = Abuf[SW128B((uint32_t)((row + 8) * 128 + (k + 4) * 4)) >> 2];
            }
#pragma unroll
            for (int ni = 0; ni < 8; ni++) {
                int n = wn * 64 + ni * 8 + lr;
                int kb = kk * 8 + lc;
                int nsw = n ^ (lc << 3);
                bf[ni].x = Bbuf[kb * 128 + nsw];
                bf[ni].y = Bbuf[(kb + 4) * 128 + nsw];
            }
#pragma unroll
            for (int mi = 0; mi < 4; mi++)
#pragma unroll
                for (int ni = 0; ni < 8; ni++) MMA_TF32(acc[mi][ni], af[mi], bf[ni]);
        }
    }
#undef G4_LOAD

#pragma unroll
    for (int mi = 0; mi < 4; mi++) {
#pragma unroll
        for (int ni = 0; ni < 8; ni++) {
            int row0 = by * 128 + wm * 64 + mi * 16 + lr;
            int col  = bx * 128 + wn * 64 + ni * 8 + lc * 2;
            float b0 = 0.f, b1 = 0.f;
            if (HASBIAS) { b0 = bias[col]; b1 = bias[col + 1]; }
            float v0 = acc[mi][ni][0] + b0, v1 = acc[mi][ni][1] + b1;
            float v2 = acc[mi][ni][2] + b0, v3 = acc[mi][ni][3] + b1;
            if (RELU) {
                v0 = fmaxf(v0, 0.f); v1 = fmaxf(v1, 0.f);
                v2 = fmaxf(v2, 0.f); v3 = fmaxf(v3, 0.f);
            }
            if (CVT) {
                v0 = f2tf32f(v0); v1 = f2tf32f(v1);
                v2 = f2tf32f(v2); v3 = f2tf32f(v3);
            }
            *(float2*)(C + (size_t)row0 * ldc + col)       = make_float2(v0, v1);
            *(float2*)(C + (size_t)(row0 + 8) * ldc + col) = make_float2(v2, v3);
        }
    }
}

// ======== score2: out[bh,i,j] = sum_d A[i][d]*B[j][d]; A,B [rows][64] tf32 ========
// CTA 128x128, 128 thr, warp 64x64, K=64 in two cp.async stages.
#define SC_SMEM (4 * 4096 * 4)
template<int MODE>
__global__ void __launch_bounds__(128) score2(
    const float* __restrict__ Qb, const float* __restrict__ Kb,
    float* __restrict__ out)
{
    const int bx = blockIdx.x, by = blockIdx.y, bh = blockIdx.z;
    const int i0 = by * 128, j0 = bx * 128;
    if (MODE == 0) { if (j0 >= i0 + 640) return; }
    else           { if (i0 + j0 < 257) return; }
    const float* A = Qb + (size_t)bh * QLEN * 64 + (size_t)i0 * 64;
    const float* B = Kb + (size_t)(MODE ? (bh & 15) : bh) * KLEN * 64 + (size_t)j0 * 64;

    extern __shared__ uint32_t dsm[];
    const uint32_t sbase = smem_u32(dsm);
    const int tid = threadIdx.x, lane = tid & 31;
    const int warp = tid >> 5, wm = warp >> 1, wn = warp & 1;

    const int a_row0 = tid >> 3, a_ch = tid & 7;
    const float* Ag = A + (size_t)a_row0 * 64 + a_ch * 4;
    const float* Bg = B + (size_t)a_row0 * 64 + a_ch * 4;

    float acc[4][8][4];
#pragma unroll
    for (int mi = 0; mi < 4; mi++)
#pragma unroll
        for (int ni = 0; ni < 8; ni++)
#pragma unroll
            for (int r = 0; r < 4; r++) acc[mi][ni][r] = 0.f;

    const int lr = lane >> 2, lc = lane & 3;

#define SC_LOAD(stg, k0) do { \
    uint32_t ab_ = sbase + (stg) * 32768; \
    uint32_t bb_ = ab_ + 16384; \
    _Pragma("unroll") for (int i = 0; i < 8; i++) { \
        uint32_t so_ = SW128B((uint32_t)((a_row0 + 16 * i) * 128 + a_ch * 16)); \
        cpasync16(ab_ + so_, Ag + (size_t)(16 * i) * 64 + (k0)); \
        cpasync16(bb_ + so_, Bg + (size_t)(16 * i) * 64 + (k0)); \
    } \
    CP_COMMIT(); \
} while (0)

    SC_LOAD(0, 0);
    SC_LOAD(1, 32);

#pragma unroll
    for (int it = 0; it < 2; it++) {
        if (it == 0) asm volatile("cp.async.wait_group 1;" ::: "memory");
        else         asm volatile("cp.async.wait_group 0;" ::: "memory");
        __syncthreads();
        const uint32_t* Abuf = dsm + it * 8192;
        const uint32_t* Bbuf = Abuf + 4096;
#pragma unroll
        for (int kk = 0; kk < 4; kk++) {
            uint4 af[4]; uint2 bf[8];
#pragma unroll
            for (int mi = 0; mi < 4; mi++) {
                int row = wm * 64 + mi * 16 + lr;
                int k = kk * 8 + lc;
                af[mi].x = Abuf[SW128B((uint32_t)(row * 128 + k * 4)) >> 2];
                af[mi].y = Abuf[SW128B((uint32_t)((row + 8) * 128 + k * 4)) >> 2];
                af[mi].z = Abuf[SW128B((uint32_t)(row * 128 + (k + 4) * 4)) >> 2];
                af[mi].w = Abuf[SW128B((uint32_t)((row + 8) * 128 + (k + 4) * 4)) >> 2];
            }
#pragma unroll
            for (int ni = 0; ni < 8; ni++) {
                int n = wn * 64 + ni * 8 + lr;
                int k = kk * 8 + lc;
                bf[ni].x = Bbuf[SW128B((uint32_t)(n * 128 + k * 4)) >> 2];
                bf[ni].y = Bbuf[SW128B((uint32_t)(n * 128 + (k + 4) * 4)) >> 2];
            }
#pragma unroll
            for (int mi = 0; mi < 4; mi++)
#pragma unroll
                for (int ni = 0; ni < 8; ni++) MMA_TF32(acc[mi][ni], af[mi], bf[ni]);
        }
    }
#undef SC_LOAD

    float* ob = out + (size_t)bh * QLEN * KLEN;
#pragma unroll
    for (int mi = 0; mi < 4; mi++)
#pragma unroll
        for (int ni = 0; ni < 8; ni++) {
            int row0 = i0 + wm * 64 + mi * 16 + lr;
            int col  = j0 + wn * 64 + ni * 8 + lc * 2;
            *(float2*)(ob + (size_t)row0 * KLEN + col) =
                make_float2(acc[mi][ni][0], acc[mi][ni][1]);
            *(float2*)(ob + (size_t)(row0 + 8) * KLEN + col) =
                make_float2(acc[mi][ni][2], acc[mi][ni][3]);
        }
}

// ======== av2: av = P[128, kmax] @ V[kmax, 64]; gemm4-style, N=64 ========
// 128 thr, warps 2x2 (64x32 each), 3-stage ring: A 4096 + B 2048 words/stage
#define AV2_STAGE_W 6144
#define AV2_SMEM (3 * AV2_STAGE_W * 4)
__global__ void __launch_bounds__(128) av2(
    const float* __restrict__ P, const float* __restrict__ V, float* __restrict__ av)
{
    extern __shared__ uint32_t dsm[];
    const uint32_t sbase = smem_u32(dsm);
    const int by = blockIdx.x, bh = blockIdx.y;
    const int b = bh >> 4, n_h = bh & 15;
    const float* A = P + (size_t)bh * QLEN * KLEN + (size_t)by * 128 * KLEN;
    const float* Bv = V + (size_t)bh * KLEN * 64;
    const int kmax = min(KLEN, by * 128 + 640);

    const int tid = threadIdx.x, lane = tid & 31;
    const int warp = tid >> 5, wm = warp >> 1, wn = warp & 1;

    const int a_row0 = tid >> 3, a_ch = tid & 7;
    const float* Ag = A + (size_t)a_row0 * KLEN + a_ch * 4;
    const int b_k = tid >> 2, b_nch0 = tid & 3;
    const float* Bg = Bv + (size_t)b_k * 64 + b_nch0 * 4;

    float acc[4][4][4];
#pragma unroll
    for (int mi = 0; mi < 4; mi++)
#pragma unroll
        for (int ni = 0; ni < 4; ni++)
#pragma unroll
            for (int r = 0; r < 4; r++) acc[mi][ni][r] = 0.f;

    const int lr = lane >> 2, lc = lane & 3;
    const int niter = kmax >> 5;

#define AV2_LOAD(stg, k0) do { \
    uint32_t ab_ = sbase + (stg) * (AV2_STAGE_W * 4); \
    _Pragma("unroll") for (int i = 0; i < 8; i++) { \
        uint32_t so_ = SW128B((uint32_t)((a_row0 + 16 * i) * 128 + a_ch * 16)); \
        cpasync16(ab_ + so_, Ag + (size_t)(16 * i) * KLEN + (k0)); \
    } \
    uint32_t bb_ = ab_ + 4096 * 4; \
    _Pragma("unroll") for (int i = 0; i < 4; i++) { \
        int n_ = (b_nch0 + 4 * i) * 4; \
        uint32_t w_ = (uint32_t)(b_k * 64 + (n_ ^ ((b_k & 3) << 3))); \
        cpasync16(bb_ + w_ * 4, Bg + (size_t)(k0) * 64 + 16 * i); \
    } \
    CP_COMMIT(); \
} while (0)

    AV2_LOAD(0, 0);
    if (niter > 1) AV2_LOAD(1, 32);

    for (int it = 0; it < niter; it++) {
        if (it + 1 < niter) {
            asm volatile("cp.async.wait_group 1;" ::: "memory");
        } else {
            asm volatile("cp.async.wait_group 0;" ::: "memory");
        }
        __syncthreads();
        if (it + 2 < niter) AV2_LOAD((it + 2) % 3, (it + 2) * 32);

        const uint32_t* Abuf = dsm + (it % 3) * AV2_STAGE_W;
        const uint32_t* Bbuf = Abuf + 4096;
#pragma unroll
        for (int kk = 0; kk < 4; kk++) {
            uint4 af[4]; uint2 bf[4];
#pragma unroll
            for (int mi = 0; mi < 4; mi++) {
                int row = wm * 64 + mi * 16 + lr;
                int k = kk * 8 + lc;
                af[mi].x = Abuf[SW128B((uint32_t)(row * 128 + k * 4)) >> 2];
                af[mi].y = Abuf[SW128B((uint32_t)((row + 8) * 128 + k * 4)) >> 2];
                af[mi].z = Abuf[SW128B((uint32_t)(row * 128 + (k + 4) * 4)) >> 2];
                af[mi].w = Abuf[SW128B((uint32_t)((row + 8) * 128 + (k + 4) * 4)) >> 2];
            }
#pragma unroll
            for (int ni = 0; ni < 4; ni++) {
                int n = wn * 32 + ni * 8 + lr;
                int kb = kk * 8 + lc;
                int nsw = n ^ (lc << 3);
                bf[ni].x = Bbuf[kb * 64 + nsw];
                bf[ni].y = Bbuf[(kb + 4) * 64 + nsw];
            }
#pragma unroll
            for (int mi = 0; mi < 4; mi++)
#pragma unroll
                for (int ni = 0; ni < 4; ni++) MMA_TF32(acc[mi][ni], af[mi], bf[ni]);
        }
    }
#undef AV2_LOAD

#pragma unroll
    for (int mi = 0; mi < 4; mi++)
#pragma unroll
        for (int ni = 0; ni < 4; ni++) {
            int row0 = by * 128 + wm * 64 + mi * 16 + lr;
            int col  = wn * 32 + ni * 8 + lc * 2;
            *(float2*)(av + ((size_t)row0 * 4 + b) * 1024 + n_h * 64 + col) =
                make_float2(f2tf32f(acc[mi][ni][0]), f2tf32f(acc[mi][ni][1]));
            *(float2*)(av + ((size_t)(row0 + 8) * 4 + b) * 1024 + n_h * 64 + col) =
                make_float2(f2tf32f(acc[mi][ni][2]), f2tf32f(acc[mi][ni][3]));
        }
}

// ---------------- weight rounding ----------------
__global__ void roundw_kernel(float4* __restrict__ dst, const float4* __restrict__ src) {
    size_t i = (size_t)blockIdx.x * 256 + threadIdx.x;
    float4 v = src[i];
    dst[i] = make_float4(f2tf32f(v.x), f2tf32f(v.y), f2tf32f(v.z), f2tf32f(v.w));
}

// ---------------- small kernels ----------------
__global__ void posemb_kernel(float* __restrict__ r) {
    int idx = blockIdx.x * 256 + threadIdx.x;
    int k = idx >> 10, d = idx & 1023;
    float pos = (float)(KLEN - 1 - k);
    int j = (d < 512) ? d : d - 512;
    float inv = expf(-((float)(2 * j) / 1024.0f) * 9.210340371976184f);
    float ang = pos * inv;
    r[idx] = f2tf32f((d < 512) ? sinf(ang) : cosf(ang));
}

__global__ void copy4_kernel(float4* __restrict__ dst, const float4* __restrict__ src) {
    size_t i = (size_t)blockIdx.x * 256 + threadIdx.x;
    dst[i] = src[i];
}

__global__ void concat_kernel(float4* __restrict__ cat, const float4* __restrict__ mem,
                              const float4* __restrict__ h) {
    size_t i = (size_t)blockIdx.x * 256 + threadIdx.x;
    const size_t half = (size_t)MLEN * BATCH * DMODEL / 4;
    float4 v = (i < half) ? mem[i] : h[i - half];
    cat[i] = make_float4(f2tf32f(v.x), f2tf32f(v.y), f2tf32f(v.z), f2tf32f(v.w));
}

// outputs pre-rounded tf32
__global__ void repack_quqv(const float* __restrict__ heads, const float* __restrict__ u,
                            const float* __restrict__ v, float* __restrict__ qu,
                            float* __restrict__ qv) {
    int idx = blockIdx.x * 256 + threadIdx.x;
    int d4 = idx & 15, i = (idx >> 4) & 511, bh = idx >> 13;
    int b = bh >> 4, n = bh & 15;
    float4 q = *(const float4*)(heads + ((size_t)((512 + i) * 4 + b)) * 3072 + n * 64 + d4 * 4);
    float4 uu = *(const float4*)(u + n * 64 + d4 * 4);
    float4 vv = *(const float4*)(v + n * 64 + d4 * 4);
    size_t o = ((size_t)bh * 512 + i) * 64 + d4 * 4;
    *(float4*)(qu + o) = make_float4(f2tf32f(q.x + uu.x), f2tf32f(q.y + uu.y),
                                     f2tf32f(q.z + uu.z), f2tf32f(q.w + uu.w));
    *(float4*)(qv + o) = make_float4(f2tf32f(q.x + vv.x), f2tf32f(q.y + vv.y),
                                     f2tf32f(q.z + vv.z), f2tf32f(q.w + vv.w));
}

__global__ void repack_kv(const float* __restrict__ heads, float* __restrict__ kc,
                          float* __restrict__ vc) {
    int idx = blockIdx.x * 256 + threadIdx.x;
    int d4 = idx & 15, j = (idx >> 4) & 1023, bh = idx >> 14;
    int b = bh >> 4, n = bh & 15;
    const float* base = heads + ((size_t)(j * 4 + b)) * 3072 + n * 64 + d4 * 4;
    float4 kx = *(const float4*)(base + 1024);
    float4 vx = *(const float4*)(base + 2048);
    size_t o = ((size_t)bh * 1024 + j) * 64 + d4 * 4;
    *(float4*)(kc + o) = kx;
    *(float4*)(vc + o) = vx;
}

__global__ void repack_rk(const float* __restrict__ rk, float* __restrict__ rkc) {
    int idx = blockIdx.x * 256 + threadIdx.x;
    int d4 = idx & 15, j = (idx >> 4) & 1023, n = idx >> 14;
    *(float4*)(rkc + ((size_t)n * 1024 + j) * 64 + d4 * 4) =
        *(const float4*)(rk + (size_t)j * 1024 + n * 64 + d4 * 4);
}

// ---------------- softmax (shift+mask+scale fused; output rounded) ----------------
__global__ void __launch_bounds__(256) softmax_kernel(float* ac, const float* __restrict__ bd) {
    int i = blockIdx.x;
    int bh = blockIdx.y;
    float* acrow = ac + ((size_t)bh * QLEN + i) * KLEN;
    const float* bdrow = bd + ((size_t)bh * QLEN + i) * KLEN;
    int tid = threadIdx.x;
    __shared__ float red[256];
    int jmax = i + MLEN;
    int shift = QLEN - 1 - i;
    float v[4];
    float m = -1e30f;
#pragma unroll
    for (int c = 0; c < 4; c++) {
        int j = c * 256 + tid;
        float s = (j <= jmax) ? 0.125f * (acrow[j] + bdrow[j + shift]) : -1e30f;
        v[c] = s;
        m = fmaxf(m, s);
    }
    red[tid] = m; __syncthreads();
    for (int o = 128; o > 0; o >>= 1) {
        if (tid < o) red[tid] = fmaxf(red[tid], red[tid + o]);
        __syncthreads();
    }
    m = red[0]; __syncthreads();
    float sum = 0.f;
#pragma unroll
    for (int c = 0; c < 4; c++) { v[c] = expf(v[c] - m); sum += v[c]; }
    red[tid] = sum; __syncthreads();
    for (int o = 128; o > 0; o >>= 1) {
        if (tid < o) red[tid] += red[tid + o];
        __syncthreads();
    }
    float inv = 1.0f / red[0];
#pragma unroll
    for (int c = 0; c < 4; c++) acrow[c * 256 + tid] = f2tf32f(v[c] * inv);
}

// ---------------- residual add + LayerNorm (output rounded) ----------------
__global__ void __launch_bounds__(256) add_ln_kernel(
    float* __restrict__ h, const float* __restrict__ t,
    const float* __restrict__ g, const float* __restrict__ b)
{
    int row = blockIdx.x;
    int tid = threadIdx.x;
    __shared__ float rs[256], rs2[256];
    float x[4];
    float s = 0.f, ss = 0.f;
#pragma unroll
    for (int c = 0; c < 4; c++) {
        int d = c * 256 + tid;
        float v = h[(size_t)row * 1024 + d] + t[(size_t)row * 1024 + d];
        x[c] = v; s += v; ss += v * v;
    }
    rs[tid] = s; rs2[tid] = ss; __syncthreads();
    for (int o = 128; o > 0; o >>= 1) {
        if (tid < o) { rs[tid] += rs[tid + o]; rs2[tid] += rs2[tid + o]; }
        __syncthreads();
    }
    float mu = rs[0] * (1.0f / 1024.0f);
    float var = rs2[0] * (1.0f / 1024.0f) - mu * mu;
    float inv = rsqrtf(var + 1e-5f);
#pragma unroll
    for (int c = 0; c < 4; c++) {
        int d = c * 256 + tid;
        h[(size_t)row * 1024 + d] = f2tf32f((x[c] - mu) * inv * g[d] + b[d]);
    }
}

// ---------------- launch ----------------
extern "C" void kernel_launch(void* const* d_in, const int* in_sizes, int n_in,
                              void* d_out, int out_size) {
    (void)in_sizes; (void)n_in; (void)out_size;
    const float* x     = (const float*)d_in[0];
    const float* mems  = (const float*)d_in[1];
    const float* u     = (const float*)d_in[2];
    const float* v     = (const float*)d_in[3];
    const float* W_qkv = (const float*)d_in[4];
    const float* W_o   = (const float*)d_in[5];
    const float* W_r   = (const float*)d_in[6];
    const float* ln1_g = (const float*)d_in[7];
    const float* ln1_b = (const float*)d_in[8];
    const float* W1    = (const float*)d_in[9];
    const float* b1    = (const float*)d_in[10];
    const float* W2    = (const float*)d_in[11];
    const float* b2    = (const float*)d_in[12];
    const float* ln2_g = (const float*)d_in[13];
    const float* ln2_b = (const float*)d_in[14];

    float *cat, *heads, *r, *rk, *ac, *bd, *av, *tmp, *h, *ff, *qu, *qv, *kc, *vc, *rkc;
    float *wqkv, *wr, *wo, *w1, *w2;
    cudaGetSymbolAddress((void**)&cat,   g_cat);
    cudaGetSymbolAddress((void**)&heads, g_heads);
    cudaGetSymbolAddress((void**)&r,     g_r);
    cudaGetSymbolAddress((void**)&rk,    g_rk);
    cudaGetSymbolAddress((void**)&ac,    g_ac);
    cudaGetSymbolAddress((void**)&bd,    g_bd);
    cudaGetSymbolAddress((void**)&av,    g_av);
    cudaGetSymbolAddress((void**)&tmp,   g_tmp);
    cudaGetSymbolAddress((void**)&h,     g_h);
    cudaGetSymbolAddress((void**)&ff,    g_ff);
    cudaGetSymbolAddress((void**)&qu,    g_qu);
    cudaGetSymbolAddress((void**)&qv,    g_qv);
    cudaGetSymbolAddress((void**)&kc,    g_kc);
    cudaGetSymbolAddress((void**)&vc,    g_vc);
    cudaGetSymbolAddress((void**)&rkc,   g_rkc);
    cudaGetSymbolAddress((void**)&wqkv,  g_wqkv);
    cudaGetSymbolAddress((void**)&wr,    g_wr);
    cudaGetSymbolAddress((void**)&wo,    g_wo);
    cudaGetSymbolAddress((void**)&w1,    g_w1);
    cudaGetSymbolAddress((void**)&w2,    g_w2);

    cudaFuncSetAttribute(gemm4<0,0,0>, cudaFuncAttributeMaxDynamicSharedMemorySize, G4_SMEM);
    cudaFuncSetAttribute(gemm4<0,0,1>, cudaFuncAttributeMaxDynamicSharedMemorySize, G4_SMEM);
    cudaFuncSetAttribute(gemm4<1,1,1>, cudaFuncAttributeMaxDynamicSharedMemorySize, G4_SMEM);
    cudaFuncSetAttribute(gemm4<0,1,0>, cudaFuncAttributeMaxDynamicSharedMemorySize, G4_SMEM);
    cudaFuncSetAttribute(score2<0>,    cudaFuncAttributeMaxDynamicSharedMemorySize, SC_SMEM);
    cudaFuncSetAttribute(score2<1>,    cudaFuncAttributeMaxDynamicSharedMemorySize, SC_SMEM);
    cudaFuncSetAttribute(av2,          cudaFuncAttributeMaxDynamicSharedMemorySize, AV2_SMEM);

    // one-time weight rounding
    roundw_kernel<<<(NLAYER*DMODEL*3072/4)/256, 256>>>((float4*)wqkv, (const float4*)W_qkv);
    roundw_kernel<<<(NLAYER*DMODEL*DMODEL/4)/256, 256>>>((float4*)wr, (const float4*)W_r);
    roundw_kernel<<<(NLAYER*DMODEL*DMODEL/4)/256, 256>>>((float4*)wo, (const float4*)W_o);
    roundw_kernel<<<(NLAYER*DMODEL*DINNER/4)/256, 256>>>((float4*)w1, (const float4*)W1);
    roundw_kernel<<<(NLAYER*DINNER*DMODEL/4)/256, 256>>>((float4*)w2, (const float4*)W2);

    posemb_kernel<<<4096, 256>>>(r);
    copy4_kernel<<<2048, 256>>>((float4*)h, (const float4*)x);

    for (int l = 0; l < NLAYER; l++) {
        const float* Wq = wqkv + (size_t)l * DMODEL * 3072;
        concat_kernel<<<4096, 256>>>((float4*)cat,
                                     (const float4*)(mems + (size_t)l * MLEN * BATCH * DMODEL),
                                     (const float4*)h);
        // K,V: all 4096 rows, cols 1024..3071 — rounded output (feeds kc/vc)
        gemm4<0,0,1><<<dim3(16, 32), 128, G4_SMEM>>>(
            cat, Wq + 1024, nullptr, heads + 1024, 1024, 1024, 3072, 3072);
        // Q: last 2048 rows — rounded output (feeds qu/qv)
        gemm4<0,0,1><<<dim3(8, 16), 128, G4_SMEM>>>(
            cat + (size_t)2048 * 1024, Wq, nullptr, heads + (size_t)2048 * 3072,
            1024, 1024, 3072, 3072);
        // rk — rounded output (feeds rkc)
        gemm4<0,0,1><<<dim3(8, 8), 128, G4_SMEM>>>(
            r, wr + (size_t)l * DMODEL * DMODEL, nullptr, rk, 1024, 1024, 1024, 1024);
        // repacks
        repack_quqv<<<2048, 256>>>(heads, u, v, qu, qv);
        repack_kv<<<4096, 256>>>(heads, kc, vc);
        repack_rk<<<1024, 256>>>(rk, rkc);
        // scores (cp.async MMA)
        score2<0><<<dim3(8, 4, BH), 128, SC_SMEM>>>(qu, kc, ac);
        score2<1><<<dim3(8, 4, BH), 128, SC_SMEM>>>(qv, rkc, bd);
        softmax_kernel<<<dim3(QLEN, BH), 256>>>(ac, bd);
        av2<<<dim3(4, BH), 128, AV2_SMEM>>>(ac, vc, av);
        // O projection
        gemm4<0,0,0><<<dim3(8, 16), 128, G4_SMEM>>>(
            av, wo + (size_t)l * DMODEL * DMODEL, nullptr, tmp, 1024, 1024, 1024, 1024);
        add_ln_kernel<<<2048, 256>>>(h, tmp, ln1_g + (size_t)l * DMODEL, ln1_b + (size_t)l * DMODEL);
        // FFN
        gemm4<1,1,1><<<dim3(32, 16), 128, G4_SMEM>>>(
            h, w1 + (size_t)l * DMODEL * DINNER, b1 + (size_t)l * DINNER, ff,
            1024, 1024, 4096, 4096);
        gemm4<0,1,0><<<dim3(8, 16), 128, G4_SMEM>>>(
            ff, w2 + (size_t)l * DINNER * DMODEL, b2 + (size_t)l * DMODEL, tmp,
            4096, 4096, 1024, 1024);
        add_ln_kernel<<<2048, 256>>>(h, tmp, ln2_g + (size_t)l * DMODEL, ln2_b + (size_t)l * DMODEL);
    }

    cudaMemcpyAsync(d_out, h, (size_t)QLEN * BATCH * DMODEL * sizeof(float),
                    cudaMemcpyDeviceToDevice);
}

// round 10
// speedup vs baseline: 2.5170x; 1.0515x over previous
#include <cuda_runtime.h>
#include <math.h>
#include <stdint.h>

#define QLEN 512
#define BATCH 4
#define DMODEL 1024
#define NLAYER 4
#define NHEAD 16
#define DHEAD 64
#define DINNER 4096
#define MLEN 512
#define KLEN 1024
#define BH (BATCH*NHEAD)

// ---------------- scratch ----------------
__device__ float g_cat[(size_t)KLEN*BATCH*DMODEL];
__device__ float g_heads[(size_t)KLEN*BATCH*3*DMODEL];
__device__ float g_r[(size_t)KLEN*DMODEL];
__device__ float g_ac[(size_t)BH*QLEN*KLEN];
__device__ float g_bd[(size_t)BH*QLEN*KLEN];
__device__ float g_av[(size_t)QLEN*BATCH*DMODEL];
__device__ float g_tmp[(size_t)QLEN*BATCH*DMODEL];
__device__ float g_tmp2[(size_t)QLEN*BATCH*DMODEL];
__device__ float g_h[(size_t)QLEN*BATCH*DMODEL];
__device__ float g_ff[(size_t)QLEN*BATCH*DINNER];
__device__ float g_qu[(size_t)BH*QLEN*DHEAD];
__device__ float g_qv[(size_t)BH*QLEN*DHEAD];
__device__ float g_kc[(size_t)BH*KLEN*DHEAD];
__device__ float g_vc[(size_t)BH*KLEN*DHEAD];
__device__ float g_rkc[(size_t)NHEAD*KLEN*DHEAD];
// tf32-rounded weight copies
__device__ float g_wqkv[(size_t)NLAYER*DMODEL*3072];
__device__ float g_wr[(size_t)NLAYER*DMODEL*DMODEL];
__device__ float g_wo[(size_t)NLAYER*DMODEL*DMODEL];
__device__ float g_w1[(size_t)NLAYER*DMODEL*DINNER];
__device__ float g_w2[(size_t)NLAYER*DINNER*DMODEL];

__device__ __forceinline__ uint32_t f2tf32(float f) {
    uint32_t o;
    asm("cvt.rna.tf32.f32 %0, %1;" : "=r"(o) : "f"(f));
    return o;
}
__device__ __forceinline__ float f2tf32f(float f) {
    uint32_t o = f2tf32(f);
    return __uint_as_float(o);
}

#define MMA_TF32(d, a, b) \
    asm volatile("mma.sync.aligned.m16n8k8.row.col.f32.tf32.tf32.f32 " \
                 "{%0,%1,%2,%3}, {%4,%5,%6,%7}, {%8,%9}, {%0,%1,%2,%3};" \
                 : "+f"(d[0]), "+f"(d[1]), "+f"(d[2]), "+f"(d[3]) \
                 : "r"(a.x), "r"(a.y), "r"(a.z), "r"(a.w), "r"(b.x), "r"(b.y))

__device__ __forceinline__ void cpasync16(uint32_t dst, const void* src) {
    asm volatile("cp.async.cg.shared.global [%0], [%1], 16;" :: "r"(dst), "l"(src));
}
#define CP_COMMIT() asm volatile("cp.async.commit_group;" ::: "memory")
__device__ __forceinline__ uint32_t smem_u32(const void* p) {
    uint32_t a;
    asm("{ .reg .u64 t; cvta.to.shared.u64 t, %1; cvt.u32.u64 %0, t; }" : "=r"(a) : "l"(p));
    return a;
}
#define SW128B(o) ((o) ^ (((o) >> 3) & 0x70))

// gemm4: 3 stages x (A 4096 + B 4096) words
#define G4_STAGE_W 8192
#define G4_SMEM (3 * G4_STAGE_W * 4)

// ======== gemm4: C[M,N]=A[M,K]@B[K,N]. 128 thr, CTA 128x128, warp 64x64 ========
// blockIdx.z = K-split index: koff = z*K, output to C0 (z=0) or C1 (z=1),
// bias applied only on z==0.
template<int RELU, int HASBIAS, int CVT>
__global__ void __launch_bounds__(128) gemm4(
    const float* __restrict__ A, const float* __restrict__ B,
    const float* __restrict__ bias, float* __restrict__ C0, float* __restrict__ C1,
    int K, int lda, int ldb, int ldc)
{
    extern __shared__ uint32_t dsm[];
    const uint32_t sbase = smem_u32(dsm);
    const int tid = threadIdx.x, lane = tid & 31;
    const int warp = tid >> 5, wm = warp >> 1, wn = warp & 1;
    const int bx = blockIdx.x, by = blockIdx.y, bz = blockIdx.z;

    const int koff = bz * K;
    float* C = bz ? C1 : C0;

    const int a_row0 = tid >> 3, a_ch = tid & 7;
    const float* Ag = A + (size_t)(by * 128 + a_row0) * lda + koff + a_ch * 4;
    const int b_k = tid >> 2, b_nch0 = tid & 3;
    const float* Bg = B + (size_t)(koff + b_k) * ldb + bx * 128 + b_nch0 * 4;

    float acc[4][8][4];
#pragma unroll
    for (int mi = 0; mi < 4; mi++)
#pragma unroll
        for (int ni = 0; ni < 8; ni++)
#pragma unroll
            for (int r = 0; r < 4; r++) acc[mi][ni][r] = 0.f;

    const int lr = lane >> 2, lc = lane & 3;
    const int niter = K >> 5;

#define G4_LOAD(stg, k0) do { \
    uint32_t ab_ = sbase + (stg) * (G4_STAGE_W * 4); \
    _Pragma("unroll") for (int i = 0; i < 8; i++) { \
        uint32_t so_ = SW128B((uint32_t)((a_row0 + 16 * i) * 128 + a_ch * 16)); \
        cpasync16(ab_ + so_, Ag + (size_t)(16 * i) * lda + (k0)); \
    } \
    uint32_t bb_ = ab_ + 4096 * 4; \
    _Pragma("unroll") for (int i = 0; i < 8; i++) { \
        int n_ = (b_nch0 + 4 * i) * 4; \
        uint32_t w_ = (uint32_t)(b_k * 128 + (n_ ^ ((b_k & 3) << 3))); \
        cpasync16(bb_ + w_ * 4, Bg + (size_t)(k0) * ldb + 16 * i); \
    } \
    CP_COMMIT(); \
} while (0)

    G4_LOAD(0, 0);
    if (niter > 1) G4_LOAD(1, 32);

    for (int it = 0; it < niter; it++) {
        if (it + 1 < niter) {
            asm volatile("cp.async.wait_group 1;" ::: "memory");
        } else {
            asm volatile("cp.async.wait_group 0;" ::: "memory");
        }
        __syncthreads();
        if (it + 2 < niter) G4_LOAD((it + 2) % 3, (it + 2) * 32);

        const uint32_t* Abuf = dsm + (it % 3) * G4_STAGE_W;
        const uint32_t* Bbuf = Abuf + 4096;
#pragma unroll
        for (int kk = 0; kk < 4; kk++) {
            uint4 af[4]; uint2 bf[8];
#pragma unroll
            for (int mi = 0; mi < 4; mi++) {
                int row = wm * 64 + mi * 16 + lr;
                int k = kk * 8 + lc;
                af[mi].x = Abuf[SW128B((uint32_t)(row * 128 + k * 4)) >> 2];
                af[mi].y = Abuf[SW128B((uint32_t)((row + 8) * 128 + k * 4)) >> 2];
                af[mi].z = Abuf[SW128B((uint32_t)(row * 128 + (k + 4) * 4)) >> 2];
                af[mi].w = Abuf[SW128B((uint32_t)((row + 8) * 128 + (k + 4) * 4)) >> 2];
            }
#pragma unroll
            for (int ni = 0; ni < 8; ni++) {
                int n = wn * 64 + ni * 8 + lr;
                int kb = kk * 8 + lc;
                int nsw = n ^ (lc << 3);
                bf[ni].x = Bbuf[kb * 128 + nsw];
                bf[ni].y = Bbuf[(kb + 4) * 128 + nsw];
            }
#pragma unroll
            for (int mi = 0; mi < 4; mi++)
#pragma unroll
                for (int ni = 0; ni < 8; ni++) MMA_TF32(acc[mi][ni], af[mi], bf[ni]);
        }
    }
#undef G4_LOAD

    const bool dobias = HASBIAS && (bz == 0);
#pragma unroll
    for (int mi = 0; mi < 4; mi++) {
#pragma unroll
        for (int ni = 0; ni < 8; ni++) {
            int row0 = by * 128 + wm * 64 + mi * 16 + lr;
            int col  = bx * 128 + wn * 64 + ni * 8 + lc * 2;
            float b0 = 0.f, b1 = 0.f;
            if (dobias) { b0 = bias[col]; b1 = bias[col + 1]; }
            float v0 = acc[mi][ni][0] + b0, v1 = acc[mi][ni][1] + b1;
            float v2 = acc[mi][ni][2] + b0, v3 = acc[mi][ni][3] + b1;
            if (RELU) {
                v0 = fmaxf(v0, 0.f); v1 = fmaxf(v1, 0.f);
                v2 = fmaxf(v2, 0.f); v3 = fmaxf(v3, 0.f);
            }
            if (CVT) {
                v0 = f2tf32f(v0); v1 = f2tf32f(v1);
                v2 = f2tf32f(v2); v3 = f2tf32f(v3);
            }
            *(float2*)(C + (size_t)row0 * ldc + col)       = make_float2(v0, v1);
            *(float2*)(C + (size_t)(row0 + 8) * ldc + col) = make_float2(v2, v3);
        }
    }
}

// ======== score2: out[bh,i,j] = sum_d A[i][d]*B[j][d] ========
#define SC_SMEM (4 * 4096 * 4)
template<int MODE>
__global__ void __launch_bounds__(128) score2(
    const float* __restrict__ Qb, const float* __restrict__ Kb,
    float* __restrict__ out)
{
    const int bx = blockIdx.x, by = blockIdx.y, bh = blockIdx.z;
    const int i0 = by * 128, j0 = bx * 128;
    if (MODE == 0) { if (j0 >= i0 + 640) return; }
    else           { if (i0 + j0 < 257) return; }
    const float* A = Qb + (size_t)bh * QLEN * 64 + (size_t)i0 * 64;
    const float* B = Kb + (size_t)(MODE ? (bh & 15) : bh) * KLEN * 64 + (size_t)j0 * 64;

    extern __shared__ uint32_t dsm[];
    const uint32_t sbase = smem_u32(dsm);
    const int tid = threadIdx.x, lane = tid & 31;
    const int warp = tid >> 5, wm = warp >> 1, wn = warp & 1;

    const int a_row0 = tid >> 3, a_ch = tid & 7;
    const float* Ag = A + (size_t)a_row0 * 64 + a_ch * 4;
    const float* Bg = B + (size_t)a_row0 * 64 + a_ch * 4;

    float acc[4][8][4];
#pragma unroll
    for (int mi = 0; mi < 4; mi++)
#pragma unroll
        for (int ni = 0; ni < 8; ni++)
#pragma unroll
            for (int r = 0; r < 4; r++) acc[mi][ni][r] = 0.f;

    const int lr = lane >> 2, lc = lane & 3;

#define SC_LOAD(stg, k0) do { \
    uint32_t ab_ = sbase + (stg) * 32768; \
    uint32_t bb_ = ab_ + 16384; \
    _Pragma("unroll") for (int i = 0; i < 8; i++) { \
        uint32_t so_ = SW128B((uint32_t)((a_row0 + 16 * i) * 128 + a_ch * 16)); \
        cpasync16(ab_ + so_, Ag + (size_t)(16 * i) * 64 + (k0)); \
        cpasync16(bb_ + so_, Bg + (size_t)(16 * i) * 64 + (k0)); \
    } \
    CP_COMMIT(); \
} while (0)

    SC_LOAD(0, 0);
    SC_LOAD(1, 32);

#pragma unroll
    for (int it = 0; it < 2; it++) {
        if (it == 0) asm volatile("cp.async.wait_group 1;" ::: "memory");
        else         asm volatile("cp.async.wait_group 0;" ::: "memory");
        __syncthreads();
        const uint32_t* Abuf = dsm + it * 8192;
        const uint32_t* Bbuf = Abuf + 4096;
#pragma unroll
        for (int kk = 0; kk < 4; kk++) {
            uint4 af[4]; uint2 bf[8];
#pragma unroll
            for (int mi = 0; mi < 4; mi++) {
                int row = wm * 64 + mi * 16 + lr;
                int k = kk * 8 + lc;
                af[mi].x = Abuf[SW128B((uint32_t)(row * 128 + k * 4)) >> 2];
                af[mi].y = Abuf[SW128B((uint32_t)((row + 8) * 128 + k * 4)) >> 2];
                af[mi].z = Abuf[SW128B((uint32_t)(row * 128 + (k + 4) * 4)) >> 2];
                af[mi].w = Abuf[SW128B((uint32_t)((row + 8) * 128 + (k + 4) * 4)) >> 2];
            }
#pragma unroll
            for (int ni = 0; ni < 8; ni++) {
                int n = wn * 64 + ni * 8 + lr;
                int k = kk * 8 + lc;
                bf[ni].x = Bbuf[SW128B((uint32_t)(n * 128 + k * 4)) >> 2];
                bf[ni].y = Bbuf[SW128B((uint32_t)(n * 128 + (k + 4) * 4)) >> 2];
            }
#pragma unroll
            for (int mi = 0; mi < 4; mi++)
#pragma unroll
                for (int ni = 0; ni < 8; ni++) MMA_TF32(acc[mi][ni], af[mi], bf[ni]);
        }
    }
#undef SC_LOAD

    float* ob = out + (size_t)bh * QLEN * KLEN;
#pragma unroll
    for (int mi = 0; mi < 4; mi++)
#pragma unroll
        for (int ni = 0; ni < 8; ni++) {
            int row0 = i0 + wm * 64 + mi * 16 + lr;
            int col  = j0 + wn * 64 + ni * 8 + lc * 2;
            *(float2*)(ob + (size_t)row0 * KLEN + col) =
                make_float2(acc[mi][ni][0], acc[mi][ni][1]);
            *(float2*)(ob + (size_t)(row0 + 8) * KLEN + col) =
                make_float2(acc[mi][ni][2], acc[mi][ni][3]);
        }
}

// ======== av2: av = P[128, kmax] @ V[kmax, 64] ========
#define AV2_STAGE_W 6144
#define AV2_SMEM (3 * AV2_STAGE_W * 4)
__global__ void __launch_bounds__(128) av2(
    const float* __restrict__ P, const float* __restrict__ V, float* __restrict__ av)
{
    extern __shared__ uint32_t dsm[];
    const uint32_t sbase = smem_u32(dsm);
    const int by = blockIdx.x, bh = blockIdx.y;
    const int b = bh >> 4, n_h = bh & 15;
    const float* A = P + (size_t)bh * QLEN * KLEN + (size_t)by * 128 * KLEN;
    const float* Bv = V + (size_t)bh * KLEN * 64;
    const int kmax = min(KLEN, by * 128 + 640);

    const int tid = threadIdx.x, lane = tid & 31;
    const int warp = tid >> 5, wm = warp >> 1, wn = warp & 1;

    const int a_row0 = tid >> 3, a_ch = tid & 7;
    const float* Ag = A + (size_t)a_row0 * KLEN + a_ch * 4;
    const int b_k = tid >> 2, b_nch0 = tid & 3;
    const float* Bg = Bv + (size_t)b_k * 64 + b_nch0 * 4;

    float acc[4][4][4];
#pragma unroll
    for (int mi = 0; mi < 4; mi++)
#pragma unroll
        for (int ni = 0; ni < 4; ni++)
#pragma unroll
            for (int r = 0; r < 4; r++) acc[mi][ni][r] = 0.f;

    const int lr = lane >> 2, lc = lane & 3;
    const int niter = kmax >> 5;

#define AV2_LOAD(stg, k0) do { \
    uint32_t ab_ = sbase + (stg) * (AV2_STAGE_W * 4); \
    _Pragma("unroll") for (int i = 0; i < 8; i++) { \
        uint32_t so_ = SW128B((uint32_t)((a_row0 + 16 * i) * 128 + a_ch * 16)); \
        cpasync16(ab_ + so_, Ag + (size_t)(16 * i) * KLEN + (k0)); \
    } \
    uint32_t bb_ = ab_ + 4096 * 4; \
    _Pragma("unroll") for (int i = 0; i < 4; i++) { \
        int n_ = (b_nch0 + 4 * i) * 4; \
        uint32_t w_ = (uint32_t)(b_k * 64 + (n_ ^ ((b_k & 3) << 3))); \
        cpasync16(bb_ + w_ * 4, Bg + (size_t)(k0) * 64 + 16 * i); \
    } \
    CP_COMMIT(); \
} while (0)

    AV2_LOAD(0, 0);
    if (niter > 1) AV2_LOAD(1, 32);

    for (int it = 0; it < niter; it++) {
        if (it + 1 < niter) {
            asm volatile("cp.async.wait_group 1;" ::: "memory");
        } else {
            asm volatile("cp.async.wait_group 0;" ::: "memory");
        }
        __syncthreads();
        if (it + 2 < niter) AV2_LOAD((it + 2) % 3, (it + 2) * 32);

        const uint32_t* Abuf = dsm + (it % 3) * AV2_STAGE_W;
        const uint32_t* Bbuf = Abuf + 4096;
#pragma unroll
        for (int kk = 0; kk < 4; kk++) {
            uint4 af[4]; uint2 bf[4];
#pragma unroll
            for (int mi = 0; mi < 4; mi++) {
                int row = wm * 64 + mi * 16 + lr;
                int k = kk * 8 + lc;
                af[mi].x = Abuf[SW128B((uint32_t)(row * 128 + k * 4)) >> 2];
                af[mi].y = Abuf[SW128B((uint32_t)((row + 8) * 128 + k * 4)) >> 2];
                af[mi].z = Abuf[SW128B((uint32_t)(row * 128 + (k + 4) * 4)) >> 2];
                af[mi].w = Abuf[SW128B((uint32_t)((row + 8) * 128 + (k + 4) * 4)) >> 2];
            }
#pragma unroll
            for (int ni = 0; ni < 4; ni++) {
                int n = wn * 32 + ni * 8 + lr;
                int kb = kk * 8 + lc;
                int nsw = n ^ (lc << 3);
                bf[ni].x = Bbuf[kb * 64 + nsw];
                bf[ni].y = Bbuf[(kb + 4) * 64 + nsw];
            }
#pragma unroll
            for (int mi = 0; mi < 4; mi++)
#pragma unroll
                for (int ni = 0; ni < 4; ni++) MMA_TF32(acc[mi][ni], af[mi], bf[ni]);
        }
    }
#undef AV2_LOAD

#pragma unroll
    for (int mi = 0; mi < 4; mi++)
#pragma unroll
        for (int ni = 0; ni < 4; ni++) {
            int row0 = by * 128 + wm * 64 + mi * 16 + lr;
            int col  = wn * 32 + ni * 8 + lc * 2;
            *(float2*)(av + ((size_t)row0 * 4 + b) * 1024 + n_h * 64 + col) =
                make_float2(f2tf32f(acc[mi][ni][0]), f2tf32f(acc[mi][ni][1]));
            *(float2*)(av + ((size_t)(row0 + 8) * 4 + b) * 1024 + n_h * 64 + col) =
                make_float2(f2tf32f(acc[mi][ni][2]), f2tf32f(acc[mi][ni][3]));
        }
}

// ---------------- weight rounding ----------------
__global__ void roundw_kernel(float4* __restrict__ dst, const float4* __restrict__ src) {
    size_t i = (size_t)blockIdx.x * 256 + threadIdx.x;
    float4 v = src[i];
    dst[i] = make_float4(f2tf32f(v.x), f2tf32f(v.y), f2tf32f(v.z), f2tf32f(v.w));
}

// ---------------- small kernels ----------------
__global__ void posemb_kernel(float* __restrict__ r) {
    int idx = blockIdx.x * 256 + threadIdx.x;
    int k = idx >> 10, d = idx & 1023;
    float pos = (float)(KLEN - 1 - k);
    int j = (d < 512) ? d : d - 512;
    float inv = expf(-((float)(2 * j) / 1024.0f) * 9.210340371976184f);
    float ang = pos * inv;
    r[idx] = f2tf32f((d < 512) ? sinf(ang) : cosf(ang));
}

__global__ void copy4_kernel(float4* __restrict__ dst, const float4* __restrict__ src) {
    size_t i = (size_t)blockIdx.x * 256 + threadIdx.x;
    dst[i] = src[i];
}

__global__ void concat_kernel(float4* __restrict__ cat, const float4* __restrict__ mem,
                              const float4* __restrict__ h) {
    size_t i = (size_t)blockIdx.x * 256 + threadIdx.x;
    const size_t half = (size_t)MLEN * BATCH * DMODEL / 4;
    float4 v = (i < half) ? mem[i] : h[i - half];
    cat[i] = make_float4(f2tf32f(v.x), f2tf32f(v.y), f2tf32f(v.z), f2tf32f(v.w));
}

// q = split-K partials q0+q1 (rows [i*4+b], 1024 cols); outputs rounded tf32
__global__ void repack_quqv(const float* __restrict__ q0, const float* __restrict__ q1,
                            const float* __restrict__ u, const float* __restrict__ v,
                            float* __restrict__ qu, float* __restrict__ qv) {
    int idx = blockIdx.x * 256 + threadIdx.x;
    int d4 = idx & 15, i = (idx >> 4) & 511, bh = idx >> 13;
    int b = bh >> 4, n = bh & 15;
    size_t qoff = ((size_t)(i * 4 + b)) * 1024 + n * 64 + d4 * 4;
    float4 qa = *(const float4*)(q0 + qoff);
    float4 qb = *(const float4*)(q1 + qoff);
    float4 uu = *(const float4*)(u + n * 64 + d4 * 4);
    float4 vv = *(const float4*)(v + n * 64 + d4 * 4);
    float qx = qa.x + qb.x, qy = qa.y + qb.y, qz = qa.z + qb.z, qw = qa.w + qb.w;
    size_t o = ((size_t)bh * 512 + i) * 64 + d4 * 4;
    *(float4*)(qu + o) = make_float4(f2tf32f(qx + uu.x), f2tf32f(qy + uu.y),
                                     f2tf32f(qz + uu.z), f2tf32f(qw + uu.w));
    *(float4*)(qv + o) = make_float4(f2tf32f(qx + vv.x), f2tf32f(qy + vv.y),
                                     f2tf32f(qz + vv.z), f2tf32f(qw + vv.w));
}

__global__ void repack_kv(const float* __restrict__ heads, float* __restrict__ kc,
                          float* __restrict__ vc) {
    int idx = blockIdx.x * 256 + threadIdx.x;
    int d4 = idx & 15, j = (idx >> 4) & 1023, bh = idx >> 14;
    int b = bh >> 4, n = bh & 15;
    const float* base = heads + ((size_t)(j * 4 + b)) * 3072 + n * 64 + d4 * 4;
    float4 kx = *(const float4*)(base + 1024);
    float4 vx = *(const float4*)(base + 2048);
    size_t o = ((size_t)bh * 1024 + j) * 64 + d4 * 4;
    *(float4*)(kc + o) = kx;
    *(float4*)(vc + o) = vx;
}

// rk = split-K partials p0+p1 ([j][1024]); output [n][j][64], rounded
__global__ void repack_rk(const float* __restrict__ p0, const float* __restrict__ p1,
                          float* __restrict__ rkc) {
    int idx = blockIdx.x * 256 + threadIdx.x;
    int d4 = idx & 15, j = (idx >> 4) & 1023, n = idx >> 14;
    size_t off = (size_t)j * 1024 + n * 64 + d4 * 4;
    float4 a = *(const float4*)(p0 + off);
    float4 b = *(const float4*)(p1 + off);
    *(float4*)(rkc + ((size_t)n * 1024 + j) * 64 + d4 * 4) =
        make_float4(f2tf32f(a.x + b.x), f2tf32f(a.y + b.y),
                    f2tf32f(a.z + b.z), f2tf32f(a.w + b.w));
}

// ---------------- softmax (shift+mask+scale fused; output rounded) ----------------
__global__ void __launch_bounds__(256) softmax_kernel(float* ac, const float* __restrict__ bd) {
    int i = blockIdx.x;
    int bh = blockIdx.y;
    float* acrow = ac + ((size_t)bh * QLEN + i) * KLEN;
    const float* bdrow = bd + ((size_t)bh * QLEN + i) * KLEN;
    int tid = threadIdx.x;
    __shared__ float red[256];
    int jmax = i + MLEN;
    int shift = QLEN - 1 - i;
    float v[4];
    float m = -1e30f;
#pragma unroll
    for (int c = 0; c < 4; c++) {
        int j = c * 256 + tid;
        float s = (j <= jmax) ? 0.125f * (acrow[j] + bdrow[j + shift]) : -1e30f;
        v[c] = s;
        m = fmaxf(m, s);
    }
    red[tid] = m; __syncthreads();
    for (int o = 128; o > 0; o >>= 1) {
        if (tid < o) red[tid] = fmaxf(red[tid], red[tid + o]);
        __syncthreads();
    }
    m = red[0]; __syncthreads();
    float sum = 0.f;
#pragma unroll
    for (int c = 0; c < 4; c++) { v[c] = expf(v[c] - m); sum += v[c]; }
    red[tid] = sum; __syncthreads();
    for (int o = 128; o > 0; o >>= 1) {
        if (tid < o) red[tid] += red[tid + o];
        __syncthreads();
    }
    float inv = 1.0f / red[0];
#pragma unroll
    for (int c = 0; c < 4; c++) acrow[c * 256 + tid] = f2tf32f(v[c] * inv);
}

// ---------------- residual + 2 partials + LayerNorm (output rounded) ----------------
__global__ void __launch_bounds__(256) add_ln3_kernel(
    float* __restrict__ h, const float* __restrict__ t0, const float* __restrict__ t1,
    const float* __restrict__ g, const float* __restrict__ b)
{
    int row = blockIdx.x;
    int tid = threadIdx.x;
    __shared__ float rs[256], rs2[256];
    float x[4];
    float s = 0.f, ss = 0.f;
#pragma unroll
    for (int c = 0; c < 4; c++) {
        int d = c * 256 + tid;
        size_t o = (size_t)row * 1024 + d;
        float v = h[o] + t0[o] + t1[o];
        x[c] = v; s += v; ss += v * v;
    }
    rs[tid] = s; rs2[tid] = ss; __syncthreads();
    for (int o = 128; o > 0; o >>= 1) {
        if (tid < o) { rs[tid] += rs[tid + o]; rs2[tid] += rs2[tid + o]; }
        __syncthreads();
    }
    float mu = rs[0] * (1.0f / 1024.0f);
    float var = rs2[0] * (1.0f / 1024.0f) - mu * mu;
    float inv = rsqrtf(var + 1e-5f);
#pragma unroll
    for (int c = 0; c < 4; c++) {
        int d = c * 256 + tid;
        h[(size_t)row * 1024 + d] = f2tf32f((x[c] - mu) * inv * g[d] + b[d]);
    }
}

// ---------------- launch ----------------
extern "C" void kernel_launch(void* const* d_in, const int* in_sizes, int n_in,
                              void* d_out, int out_size) {
    (void)in_sizes; (void)n_in; (void)out_size;
    const float* x     = (const float*)d_in[0];
    const float* mems  = (const float*)d_in[1];
    const float* u     = (const float*)d_in[2];
    const float* v     = (const float*)d_in[3];
    const float* W_qkv = (const float*)d_in[4];
    const float* W_o   = (const float*)d_in[5];
    const float* W_r   = (const float*)d_in[6];
    const float* ln1_g = (const float*)d_in[7];
    const float* ln1_b = (const float*)d_in[8];
    const float* W1    = (const float*)d_in[9];
    const float* b1    = (const float*)d_in[10];
    const float* W2    = (const float*)d_in[11];
    const float* b2    = (const float*)d_in[12];
    const float* ln2_g = (const float*)d_in[13];
    const float* ln2_b = (const float*)d_in[14];

    float *cat, *heads, *r, *ac, *bd, *av, *tmp, *tmp2, *h, *ff, *qu, *qv, *kc, *vc, *rkc;
    float *wqkv, *wr, *wo, *w1, *w2;
    cudaGetSymbolAddress((void**)&cat,   g_cat);
    cudaGetSymbolAddress((void**)&heads, g_heads);
    cudaGetSymbolAddress((void**)&r,     g_r);
    cudaGetSymbolAddress((void**)&ac,    g_ac);
    cudaGetSymbolAddress((void**)&bd,    g_bd);
    cudaGetSymbolAddress((void**)&av,    g_av);
    cudaGetSymbolAddress((void**)&tmp,   g_tmp);
    cudaGetSymbolAddress((void**)&tmp2,  g_tmp2);
    cudaGetSymbolAddress((void**)&h,     g_h);
    cudaGetSymbolAddress((void**)&ff,    g_ff);
    cudaGetSymbolAddress((void**)&qu,    g_qu);
    cudaGetSymbolAddress((void**)&qv,    g_qv);
    cudaGetSymbolAddress((void**)&kc,    g_kc);
    cudaGetSymbolAddress((void**)&vc,    g_vc);
    cudaGetSymbolAddress((void**)&rkc,   g_rkc);
    cudaGetSymbolAddress((void**)&wqkv,  g_wqkv);
    cudaGetSymbolAddress((void**)&wr,    g_wr);
    cudaGetSymbolAddress((void**)&wo,    g_wo);
    cudaGetSymbolAddress((void**)&w1,    g_w1);
    cudaGetSymbolAddress((void**)&w2,    g_w2);

    cudaFuncSetAttribute(gemm4<0,0,0>, cudaFuncAttributeMaxDynamicSharedMemorySize, G4_SMEM);
    cudaFuncSetAttribute(gemm4<0,0,1>, cudaFuncAttributeMaxDynamicSharedMemorySize, G4_SMEM);
    cudaFuncSetAttribute(gemm4<1,1,1>, cudaFuncAttributeMaxDynamicSharedMemorySize, G4_SMEM);
    cudaFuncSetAttribute(gemm4<0,1,0>, cudaFuncAttributeMaxDynamicSharedMemorySize, G4_SMEM);
    cudaFuncSetAttribute(score2<0>,    cudaFuncAttributeMaxDynamicSharedMemorySize, SC_SMEM);
    cudaFuncSetAttribute(score2<1>,    cudaFuncAttributeMaxDynamicSharedMemorySize, SC_SMEM);
    cudaFuncSetAttribute(av2,          cudaFuncAttributeMaxDynamicSharedMemorySize, AV2_SMEM);

    // one-time weight rounding
    roundw_kernel<<<(NLAYER*DMODEL*3072/4)/256, 256>>>((float4*)wqkv, (const float4*)W_qkv);
    roundw_kernel<<<(NLAYER*DMODEL*DMODEL/4)/256, 256>>>((float4*)wr, (const float4*)W_r);
    roundw_kernel<<<(NLAYER*DMODEL*DMODEL/4)/256, 256>>>((float4*)wo, (const float4*)W_o);
    roundw_kernel<<<(NLAYER*DMODEL*DINNER/4)/256, 256>>>((float4*)w1, (const float4*)W1);
    roundw_kernel<<<(NLAYER*DINNER*DMODEL/4)/256, 256>>>((float4*)w2, (const float4*)W2);

    posemb_kernel<<<4096, 256>>>(r);
    copy4_kernel<<<2048, 256>>>((float4*)h, (const float4*)x);

    for (int l = 0; l < NLAYER; l++) {
        const float* Wq = wqkv + (size_t)l * DMODEL * 3072;
        concat_kernel<<<4096, 256>>>((float4*)cat,
                                     (const float4*)(mems + (size_t)l * MLEN * BATCH * DMODEL),
                                     (const float4*)h);
        // K,V: all 4096 rows, cols 1024..3071 — rounded output (feeds kc/vc)
        gemm4<0,0,1><<<dim3(16, 32, 1), 128, G4_SMEM>>>(
            cat, Wq + 1024, nullptr, heads + 1024, nullptr, 1024, 1024, 3072, 3072);
        // Q: last 2048 rows, split-K=2 into tmp/tmp2 (unrounded partials)
        gemm4<0,0,0><<<dim3(8, 16, 2), 128, G4_SMEM>>>(
            cat + (size_t)2048 * 1024, Wq, nullptr, tmp, tmp2, 512, 1024, 3072, 1024);
        // rk: split-K=2 into bd scratch halves (bd is free until score2<1>)
        gemm4<0,0,0><<<dim3(8, 8, 2), 128, G4_SMEM>>>(
            r, wr + (size_t)l * DMODEL * DMODEL, nullptr, bd, bd + (size_t)1024 * 1024,
            512, 1024, 1024, 1024);
        // repacks (sum split partials, round)
        repack_quqv<<<2048, 256>>>(tmp, tmp2, u, v, qu, qv);
        repack_kv<<<4096, 256>>>(heads, kc, vc);
        repack_rk<<<1024, 256>>>(bd, bd + (size_t)1024 * 1024, rkc);
        // scores
        score2<0><<<dim3(8, 4, BH), 128, SC_SMEM>>>(qu, kc, ac);
        score2<1><<<dim3(8, 4, BH), 128, SC_SMEM>>>(qv, rkc, bd);
        softmax_kernel<<<dim3(QLEN, BH), 256>>>(ac, bd);
        av2<<<dim3(4, BH), 128, AV2_SMEM>>>(ac, vc, av);
        // O projection: split-K=2
        gemm4<0,0,0><<<dim3(8, 16, 2), 128, G4_SMEM>>>(
            av, wo + (size_t)l * DMODEL * DMODEL, nullptr, tmp, tmp2,
            512, 1024, 1024, 1024);
        add_ln3_kernel<<<2048, 256>>>(h, tmp, tmp2,
                                      ln1_g + (size_t)l * DMODEL, ln1_b + (size_t)l * DMODEL);
        // FFN
        gemm4<1,1,1><<<dim3(32, 16, 1), 128, G4_SMEM>>>(
            h, w1 + (size_t)l * DMODEL * DINNER, b1 + (size_t)l * DINNER, ff, nullptr,
            1024, 1024, 4096, 4096);
        // FF2: split-K=2 (bias on z=0 only; b2 is part of the sum)
        gemm4<0,1,0><<<dim3(8, 16, 2), 128, G4_SMEM>>>(
            ff, w2 + (size_t)l * DINNER * DMODEL, b2 + (size_t)l * DMODEL, tmp, tmp2,
            2048, 4096, 1024, 1024);
        add_ln3_kernel<<<2048, 256>>>(h, tmp, tmp2,
                                      ln2_g + (size_t)l * DMODEL, ln2_b + (size_t)l * DMODEL);
    }

    cudaMemcpyAsync(d_out, h, (size_t)QLEN * BATCH * DMODEL * sizeof(float),
                    cudaMemcpyDeviceToDevice);
}